// round 14
// baseline (speedup 1.0000x reference)
#include <cuda_runtime.h>
#include <cuda_bf16.h>
#include <cuda_fp16.h>
#include <math.h>

#define BATCH  8
#define SEQ    1024
#define DMODEL 512
#define NHEAD  8
#define DHEAD  64
#define NLAYER 6
#define DFF    2048
#define NTOK   (BATCH*SEQ)

// ---- GEMM tiling: CTA 128x128, KC=64, 6-matrix 3-form stages ----
#define TM 128
#define TN 128
#define KC 64
#define PADK 72                       // 144B row, 16B-aligned, conflict-free
#define MATB (128*PADK*2)             // 18432 per matrix per stage
#define M_AHB 0
#define M_AHH (1*MATB)
#define M_ALH (2*MATB)
#define M_BHB (3*MATB)
#define M_BHH (4*MATB)
#define M_BLH (5*MATB)
#define STAGE_BYTES (6*MATB)          // 110592
#define GEMM_SMEM (2*STAGE_BYTES)     // 221184

#define LOSCALE 16.0f
#define INV_LOSCALE 0.0625f

// ---- flash attention tiling (R12 proven) ----
#define FPAD 72
#define NTILE 16
#define Q_HI 0
#define Q_LO 9216
#define FSTG(s) (18432 + (s)*18560)
#define KS_HI(s) (FSTG(s))
#define KS_LO(s) (FSTG(s)+4608)
#define VS_HI(s) (FSTG(s)+9216)
#define VS_LO(s) (FSTG(s)+13824)
#define BI_F(s)  (FSTG(s)+18432)
#define FLASH_SMEM (2*(18432 + 2*18560))   // 111104 bytes

// ---------------- scratch (device globals) ----------------
__device__ float g_x     [(size_t)NTOK*DMODEL];
__device__ __nv_bfloat16 g_xhb[(size_t)NTOK*DMODEL];
__device__ __half        g_xhh[(size_t)NTOK*DMODEL];
__device__ __half        g_xlh[(size_t)NTOK*DMODEL];
__device__ __nv_bfloat16 g_qkvhi[(size_t)NTOK*3*DMODEL];
__device__ __nv_bfloat16 g_qkvlo[(size_t)NTOK*3*DMODEL];
__device__ float g_kbias [(size_t)BATCH*SEQ];
__device__ __nv_bfloat16 g_aohb[(size_t)NTOK*DMODEL];
__device__ __half        g_aohh[(size_t)NTOK*DMODEL];
__device__ __half        g_aolh[(size_t)NTOK*DMODEL];
__device__ float g_tmp   [(size_t)NTOK*DMODEL];
__device__ __nv_bfloat16 g_fhb[(size_t)NTOK*DFF];
__device__ __half        g_fhh[(size_t)NTOK*DFF];
__device__ __half        g_flh[(size_t)NTOK*DFF];
// weights 3-form, [N,K] per layer
__device__ __nv_bfloat16 g_wqhb[(size_t)NLAYER*3*DMODEL*DMODEL];
__device__ __half        g_wqhh[(size_t)NLAYER*3*DMODEL*DMODEL];
__device__ __half        g_wqlh[(size_t)NLAYER*3*DMODEL*DMODEL];
__device__ __nv_bfloat16 g_wfhb[(size_t)NLAYER*DMODEL*DMODEL];
__device__ __half        g_wfhh[(size_t)NLAYER*DMODEL*DMODEL];
__device__ __half        g_wflh[(size_t)NLAYER*DMODEL*DMODEL];
__device__ __nv_bfloat16 g_w1hb[(size_t)NLAYER*DFF*DMODEL];
__device__ __half        g_w1hh[(size_t)NLAYER*DFF*DMODEL];
__device__ __half        g_w1lh[(size_t)NLAYER*DFF*DMODEL];
__device__ __nv_bfloat16 g_w2hb[(size_t)NLAYER*DMODEL*DFF];
__device__ __half        g_w2hh[(size_t)NLAYER*DMODEL*DFF];
__device__ __half        g_w2lh[(size_t)NLAYER*DMODEL*DFF];

// ---------------- helpers ----------------
__device__ __forceinline__ unsigned smem_u32(const void* p){
    unsigned a;
    asm("{ .reg .u64 t; cvta.to.shared.u64 t, %1; cvt.u32.u64 %0, t; }":"=r"(a):"l"(p));
    return a;
}
__device__ __forceinline__ void cp16(unsigned saddr, const void* g){
    asm volatile("cp.async.ca.shared.global [%0], [%1], 16;" :: "r"(saddr), "l"(g));
}
#define CP_COMMIT() asm volatile("cp.async.commit_group;" ::: "memory")
template<int N> __device__ __forceinline__ void cp_wait(){
    asm volatile("cp.async.wait_group %0;" :: "n"(N) : "memory");
}
__device__ __forceinline__ void mma16816(float* d, const unsigned* a, const unsigned* b){
    asm volatile(
        "mma.sync.aligned.m16n8k16.row.col.f32.bf16.bf16.f32 "
        "{%0,%1,%2,%3}, {%4,%5,%6,%7}, {%8,%9}, {%0,%1,%2,%3};"
        : "+f"(d[0]), "+f"(d[1]), "+f"(d[2]), "+f"(d[3])
        : "r"(a[0]), "r"(a[1]), "r"(a[2]), "r"(a[3]), "r"(b[0]), "r"(b[1]));
}
// f16-accumulate MMA (half inputs, half accum)
__device__ __forceinline__ void mma16816h(unsigned* d, const unsigned* a, const unsigned* b){
    asm volatile(
        "mma.sync.aligned.m16n8k16.row.col.f16.f16.f16.f16 "
        "{%0,%1}, {%2,%3,%4,%5}, {%6,%7}, {%0,%1};"
        : "+r"(d[0]), "+r"(d[1])
        : "r"(a[0]), "r"(a[1]), "r"(a[2]), "r"(a[3]), "r"(b[0]), "r"(b[1]));
}
__device__ __forceinline__ void ldsm4(unsigned* r, unsigned saddr){
    asm volatile("ldmatrix.sync.aligned.m8n8.x4.shared.b16 {%0,%1,%2,%3}, [%4];"
        : "=r"(r[0]), "=r"(r[1]), "=r"(r[2]), "=r"(r[3]) : "r"(saddr));
}
__device__ __forceinline__ void ldsm4t(unsigned* r, unsigned saddr){
    asm volatile("ldmatrix.sync.aligned.m8n8.x4.trans.shared.b16 {%0,%1,%2,%3}, [%4];"
        : "=r"(r[0]), "=r"(r[1]), "=r"(r[2]), "=r"(r[3]) : "r"(saddr));
}
__device__ __forceinline__ void split_bf16(float v, __nv_bfloat16& h, __nv_bfloat16& l){
    h = __float2bfloat16(v);
    l = __float2bfloat16(v - __bfloat162float(h));
}
__device__ __forceinline__ void split2(float a, float b, unsigned& hi, unsigned& lo){
    __nv_bfloat16 ha = __float2bfloat16(a), hb = __float2bfloat16(b);
    __nv_bfloat162 hp; hp.x = ha; hp.y = hb;
    __nv_bfloat162 lp;
    lp.x = __float2bfloat16(a - __bfloat162float(ha));
    lp.y = __float2bfloat16(b - __bfloat162float(hb));
    hi = *(unsigned*)&hp; lo = *(unsigned*)&lp;
}
// 3-form: bf16 hi + f16 hi + f16 lo*16  (packed x2 words)
__device__ __forceinline__ void split3x2(float a, float b,
                                         unsigned& whb, unsigned& whh, unsigned& wlh){
    __nv_bfloat16 ha = __float2bfloat16(a), hb2 = __float2bfloat16(b);
    float fa = __bfloat162float(ha), fb = __bfloat162float(hb2);
    __nv_bfloat162 hp; hp.x = ha; hp.y = hb2;
    whb = *(unsigned*)&hp;
    __half2 hh = __floats2half2_rn(fa, fb);
    whh = *(unsigned*)&hh;
    __half2 lh = __floats2half2_rn((a - fa)*LOSCALE, (b - fb)*LOSCALE);
    wlh = *(unsigned*)&lh;
}

// ---------------- merged weight prep: 3-form outputs ----------------
__global__ __launch_bounds__(256) void wprep_all_kernel(
    const float* __restrict__ Wq, const float* __restrict__ Wf,
    const float* __restrict__ W1, const float* __restrict__ W2,
    __nv_bfloat16* __restrict__ qhb, __half* __restrict__ qhh, __half* __restrict__ qlh,
    __nv_bfloat16* __restrict__ fhb, __half* __restrict__ fhh, __half* __restrict__ flh,
    __nv_bfloat16* __restrict__ w1hb, __half* __restrict__ w1hh, __half* __restrict__ w1lh,
    __nv_bfloat16* __restrict__ w2hb, __half* __restrict__ w2hh, __half* __restrict__ w2lh)
{
    __shared__ float tf[32][33];
    int id = blockIdx.x;
    const float* W; __nv_bfloat16* Tb; __half *Thh, *Tlh; int K, N;
    if (id < 4608)        { W = Wq; Tb = qhb;  Thh = qhh;  Tlh = qlh;  K = 512;  N = 1536; }
    else if (id < 6144)   { id -= 4608;  W = Wf; Tb = fhb;  Thh = fhh;  Tlh = flh;  K = 512;  N = 512; }
    else if (id < 12288)  { id -= 6144;  W = W1; Tb = w1hb; Thh = w1hh; Tlh = w1lh; K = 512;  N = 2048; }
    else                  { id -= 12288; W = W2; Tb = w2hb; Thh = w2hh; Tlh = w2lh; K = 2048; N = 512; }
    const int tilesN = N >> 5, tilesK = K >> 5;
    const int l = id / (tilesN*tilesK);
    const int rem = id - l*(tilesN*tilesK);
    const int n0 = (rem % tilesN)*32, k0 = (rem / tilesN)*32;
    const int tx = threadIdx.x & 31, ty = threadIdx.x >> 5;
    const float* Wl = W + (size_t)l*K*N;
#pragma unroll
    for (int i = 0; i < 4; i++) {
        int k = k0 + ty*4 + i;
        tf[ty*4+i][tx] = Wl[(size_t)k*N + n0 + tx];
    }
    __syncthreads();
    __nv_bfloat16* Tbl = Tb + (size_t)l*K*N;
    __half* Thl = Thh + (size_t)l*K*N;
    __half* Tll = Tlh + (size_t)l*K*N;
#pragma unroll
    for (int i = 0; i < 4; i++) {
        int n = n0 + ty*4 + i;
        float v = tf[tx][ty*4+i];
        __nv_bfloat16 h = __float2bfloat16(v);
        float hf = __bfloat162float(h);
        Tbl[(size_t)n*K + k0 + tx] = h;
        Thl[(size_t)n*K + k0 + tx] = __float2half_rn(hf);
        Tll[(size_t)n*K + k0 + tx] = __float2half_rn((v - hf)*LOSCALE);
    }
}

// ---------------- mma.sync mixed-accum split GEMM ----------------
// main: bf16 hi x bf16 hi -> f32 accum; cross: f16 hi x f16 lo*16 (both ways) -> one f16 accum.
// EPI: 1 +bias fp32 out; 2 +bias+relu 3-form out; 3 bf16 hi/lo pair out (for flash).
template<int EPI>
__global__ __launch_bounds__(256, 1) void mma_gemm_kernel(
    const __nv_bfloat16* __restrict__ Ahb, const __half* __restrict__ Ahh, const __half* __restrict__ Alh,
    const __nv_bfloat16* __restrict__ Bhb, const __half* __restrict__ Bhh, const __half* __restrict__ Blh,
    const float* __restrict__ bias,
    float* __restrict__ Cf,
    __nv_bfloat16* __restrict__ Cbh, __nv_bfloat16* __restrict__ Cbl,
    __half* __restrict__ Chh, __half* __restrict__ Clh,
    int N, int K)
{
    extern __shared__ char smem[];
    const unsigned sbase = smem_u32(smem);
    const int tid = threadIdx.x;
    const int wid = tid >> 5, lane = tid & 31;
    const int wr = wid & 3;
    const int wc = wid >> 2;
    const int bm = blockIdx.y * TM;
    const int bn = blockIdx.x * TN;

    const int la7  = lane & 7;
    const int la8  = (lane >> 3) & 1;
    const int la16 = lane >> 4;
    const unsigned aoff = (unsigned)((wr*32 + la7 + la8*8)*PADK + la16*8) * 2u;
    const unsigned boff = (unsigned)((wc*64 + la16*8 + la7)*PADK + la8*8) * 2u;

    const int lr = tid >> 3;
    const int lg = tid & 7;

    float acc[2][8][4];
    unsigned cx[2][8][2];
#pragma unroll
    for (int ma = 0; ma < 2; ma++)
#pragma unroll
        for (int na = 0; na < 8; na++) {
#pragma unroll
            for (int j = 0; j < 4; j++) acc[ma][na][j] = 0.0f;
            cx[ma][na][0] = 0u; cx[ma][na][1] = 0u;
        }

    const int NC = K >> 6;

    auto prefetch = [&](int c, int buf){
        const unsigned st = sbase + buf*STAGE_BYTES;
        const int k0 = c*KC;
#pragma unroll
        for (int i = 0; i < 4; i++) {
            int r = lr + i*32;
            unsigned so = (unsigned)(r*144 + lg*16);
            size_t ga = (size_t)(bm + r)*K + k0 + lg*8;
            size_t gb = (size_t)(bn + r)*K + k0 + lg*8;
            cp16(st + M_AHB + so, Ahb + ga);
            cp16(st + M_AHH + so, Ahh + ga);
            cp16(st + M_ALH + so, Alh + ga);
            cp16(st + M_BHB + so, Bhb + gb);
            cp16(st + M_BHH + so, Bhh + gb);
            cp16(st + M_BLH + so, Blh + gb);
        }
    };

    prefetch(0, 0);
    CP_COMMIT();

    for (int c = 0; c < NC; c++) {
        if (c + 1 < NC) { prefetch(c+1, (c+1)&1); CP_COMMIT(); cp_wait<1>(); }
        else            { cp_wait<0>(); }
        __syncthreads();

        const unsigned stg = sbase + (c & 1)*STAGE_BYTES;
        const unsigned sAhb = stg + M_AHB + aoff;
        const unsigned sAhh = stg + M_AHH + aoff;
        const unsigned sAlh = stg + M_ALH + aoff;
        const unsigned sBhb = stg + M_BHB + boff;
        const unsigned sBhh = stg + M_BHH + boff;
        const unsigned sBlh = stg + M_BLH + boff;

#pragma unroll
        for (int ks = 0; ks < 4; ks++) {
            const unsigned kb = (unsigned)(ks*32);
            unsigned ahb[2][4], ahh[2][4], alh[2][4];
#pragma unroll
            for (int ma = 0; ma < 2; ma++) {
                ldsm4(ahb[ma], sAhb + (unsigned)(ma*16*PADK*2) + kb);
                ldsm4(ahh[ma], sAhh + (unsigned)(ma*16*PADK*2) + kb);
                ldsm4(alh[ma], sAlh + (unsigned)(ma*16*PADK*2) + kb);
            }
            unsigned bhb[4][4], bhh[4][4], blh[4][4];
#pragma unroll
            for (int nb = 0; nb < 4; nb++) {
                ldsm4(bhb[nb], sBhb + (unsigned)(nb*16*PADK*2) + kb);
                ldsm4(bhh[nb], sBhh + (unsigned)(nb*16*PADK*2) + kb);
                ldsm4(blh[nb], sBlh + (unsigned)(nb*16*PADK*2) + kb);
            }
            // main product: f32 accum
#pragma unroll
            for (int ma = 0; ma < 2; ma++)
#pragma unroll
                for (int na = 0; na < 8; na++)
                    mma16816(acc[ma][na], ahb[ma], &bhb[na>>1][(na&1)*2]);
            // cross 1: Ahi(f16) x Blo(f16*16) -> f16 accum
#pragma unroll
            for (int ma = 0; ma < 2; ma++)
#pragma unroll
                for (int na = 0; na < 8; na++)
                    mma16816h(cx[ma][na], ahh[ma], &blh[na>>1][(na&1)*2]);
            // cross 2: Alo(f16*16) x Bhi(f16) -> same f16 accum
#pragma unroll
            for (int ma = 0; ma < 2; ma++)
#pragma unroll
                for (int na = 0; na < 8; na++)
                    mma16816h(cx[ma][na], alh[ma], &bhh[na>>1][(na&1)*2]);
        }
        __syncthreads();
    }

    constexpr bool HASBIAS = (EPI == 1 || EPI == 2);
    constexpr bool RELU    = (EPI == 2);
#pragma unroll
    for (int ma = 0; ma < 2; ma++) {
        const int r0 = bm + wr*32 + ma*16 + (lane >> 2);
#pragma unroll
        for (int na = 0; na < 8; na++) {
            const int cc = bn + wc*64 + na*8 + (lane & 3)*2;
            float2 c01 = __half22float2(*(__half2*)&cx[ma][na][0]);
            float2 c23 = __half22float2(*(__half2*)&cx[ma][na][1]);
            float v0 = acc[ma][na][0] + c01.x*INV_LOSCALE;
            float v1 = acc[ma][na][1] + c01.y*INV_LOSCALE;
            float v2 = acc[ma][na][2] + c23.x*INV_LOSCALE;
            float v3 = acc[ma][na][3] + c23.y*INV_LOSCALE;
            if (HASBIAS) {
                float2 bv = *(const float2*)(bias + cc);
                v0 += bv.x; v1 += bv.y; v2 += bv.x; v3 += bv.y;
            }
            if (RELU) {
                v0 = fmaxf(v0, 0.0f); v1 = fmaxf(v1, 0.0f);
                v2 = fmaxf(v2, 0.0f); v3 = fmaxf(v3, 0.0f);
            }
            if (EPI == 3) {
                unsigned hi, lo;
                split2(v0, v1, hi, lo);
                *(unsigned*)(Cbh + (size_t)r0*N + cc) = hi;
                *(unsigned*)(Cbl + (size_t)r0*N + cc) = lo;
                split2(v2, v3, hi, lo);
                *(unsigned*)(Cbh + (size_t)(r0+8)*N + cc) = hi;
                *(unsigned*)(Cbl + (size_t)(r0+8)*N + cc) = lo;
            } else if (EPI == 2) {
                unsigned whb, whh, wlh;
                split3x2(v0, v1, whb, whh, wlh);
                *(unsigned*)(Cbh + (size_t)r0*N + cc) = whb;
                *(unsigned*)(Chh + (size_t)r0*N + cc) = whh;
                *(unsigned*)(Clh + (size_t)r0*N + cc) = wlh;
                split3x2(v2, v3, whb, whh, wlh);
                *(unsigned*)(Cbh + (size_t)(r0+8)*N + cc) = whb;
                *(unsigned*)(Chh + (size_t)(r0+8)*N + cc) = whh;
                *(unsigned*)(Clh + (size_t)(r0+8)*N + cc) = wlh;
            } else {
                *(float2*)(Cf + (size_t)r0*N + cc)     = make_float2(v0, v1);
                *(float2*)(Cf + (size_t)(r0+8)*N + cc) = make_float2(v2, v3);
            }
        }
    }
}

// ---------------- fused flash attention (exact R12 winner; epilogue -> 3-form) ----------------
__global__ __launch_bounds__(256, 1) void flash_kernel(
    const __nv_bfloat16* __restrict__ qhi, const __nv_bfloat16* __restrict__ qlo,
    const float* __restrict__ kbias,
    __nv_bfloat16* __restrict__ ohb, __half* __restrict__ ohh, __half* __restrict__ olh)
{
    extern __shared__ char smraw[];
    __nv_bfloat16* sm = (__nv_bfloat16*)smraw;
    const unsigned sb = smem_u32(sm);
    const int tid = threadIdx.x, wid = tid >> 5, lane = tid & 31;
    const int bh = blockIdx.y, b = bh >> 3, h = bh & 7;
    const int q0 = blockIdx.x * 128;
    const int koff = (lane & 3)*2;
    const int r_base = wid*16 + (lane >> 2);

    const int la7  = lane & 7;
    const int la8  = (lane >> 3) & 1;
    const int la16 = lane >> 4;
    const unsigned qoff = (unsigned)((wid*16 + la7 + la8*8)*FPAD + la16*8) * 2u;
    const unsigned kboff = (unsigned)((la16*8 + la7)*FPAD + la8*8) * 2u;
    const unsigned vboff = (unsigned)((la8*8 + la7)*FPAD + la16*8) * 2u;

    auto prefetch_kv = [&](int t, int s){
        const int g = tid & 7;
        const int kt0 = t*64;
#pragma unroll
        for (int i = 0; i < 2; i++) {
            int r = (tid >> 3) + i*32;
            size_t gk = (size_t)(b*SEQ + kt0 + r)*1536 + 512 + h*64 + g*8;
            cp16(sb + 2*(KS_HI(s) + r*FPAD + g*8), qhi + gk);
            cp16(sb + 2*(KS_LO(s) + r*FPAD + g*8), qlo + gk);
            size_t gv = (size_t)(b*SEQ + kt0 + r)*1536 + 1024 + h*64 + g*8;
            cp16(sb + 2*(VS_HI(s) + r*FPAD + g*8), qhi + gv);
            cp16(sb + 2*(VS_LO(s) + r*FPAD + g*8), qlo + gv);
        }
        if (tid >= 240) {
            int j = tid - 240;
            cp16(sb + 2*BI_F(s) + j*16, kbias + b*SEQ + kt0 + j*4);
        }
    };

    {
        const int g = tid & 7;
#pragma unroll
        for (int i = 0; i < 4; i++) {
            int r = (tid >> 3) + i*32;
            size_t gq = (size_t)(b*SEQ + q0 + r)*1536 + h*64 + g*8;
            cp16(sb + 2*(Q_HI + r*FPAD + g*8), qhi + gq);
            cp16(sb + 2*(Q_LO + r*FPAD + g*8), qlo + gq);
        }
        prefetch_kv(0, 0);
        CP_COMMIT();
    }

    float m0 = -1e30f, m1 = -1e30f, l0 = 0.0f, l1 = 0.0f;
    float acc_o[8][4];
#pragma unroll
    for (int na = 0; na < 8; na++)
#pragma unroll
        for (int j = 0; j < 4; j++) acc_o[na][j] = 0.0f;

    for (int t = 0; t < NTILE; t++) {
        if (t + 1 < NTILE) { prefetch_kv(t+1, (t+1)&1); CP_COMMIT(); cp_wait<1>(); }
        else               { cp_wait<0>(); }
        __syncthreads();
        const int s = t & 1;
        const unsigned sQh = sb + 2*Q_HI + qoff;
        const unsigned sQl = sb + 2*Q_LO + qoff;
        const unsigned sKh = sb + 2*KS_HI(s) + kboff;
        const unsigned sKl = sb + 2*KS_LO(s) + kboff;
        const unsigned sVh = sb + 2*VS_HI(s) + vboff;
        const unsigned sVl = sb + 2*VS_LO(s) + vboff;
        const float* bsm = (const float*)(sm + BI_F(s));

        float sc[8][4];
#pragma unroll
        for (int na = 0; na < 8; na++)
#pragma unroll
            for (int j = 0; j < 4; j++) sc[na][j] = 0.0f;

#pragma unroll
        for (int kc = 0; kc < 4; kc++) {
            const unsigned kb = (unsigned)(kc*32);
            unsigned ah[4], al[4];
            ldsm4(ah, sQh + kb);
            ldsm4(al, sQl + kb);
            unsigned kbh[4][4], kbl[4][4];
#pragma unroll
            for (int nb = 0; nb < 4; nb++) {
                ldsm4(kbh[nb], sKh + (unsigned)(nb*16*FPAD*2) + kb);
                ldsm4(kbl[nb], sKl + (unsigned)(nb*16*FPAD*2) + kb);
            }
#pragma unroll
            for (int na = 0; na < 8; na++)
                mma16816(sc[na], ah, &kbh[na>>1][(na&1)*2]);
#pragma unroll
            for (int na = 0; na < 8; na++)
                mma16816(sc[na], ah, &kbl[na>>1][(na&1)*2]);
#pragma unroll
            for (int na = 0; na < 8; na++)
                mma16816(sc[na], al, &kbh[na>>1][(na&1)*2]);
        }

#pragma unroll
        for (int na = 0; na < 8; na++) {
            float b0 = bsm[na*8 + koff], b1 = bsm[na*8 + koff + 1];
            sc[na][0] += b0; sc[na][1] += b1;
            sc[na][2] += b0; sc[na][3] += b1;
        }

        float mx0 = -1e30f, mx1 = -1e30f;
#pragma unroll
        for (int na = 0; na < 8; na++) {
            mx0 = fmaxf(mx0, fmaxf(sc[na][0], sc[na][1]));
            mx1 = fmaxf(mx1, fmaxf(sc[na][2], sc[na][3]));
        }
        mx0 = fmaxf(mx0, __shfl_xor_sync(0xffffffffu, mx0, 1));
        mx0 = fmaxf(mx0, __shfl_xor_sync(0xffffffffu, mx0, 2));
        mx1 = fmaxf(mx1, __shfl_xor_sync(0xffffffffu, mx1, 1));
        mx1 = fmaxf(mx1, __shfl_xor_sync(0xffffffffu, mx1, 2));
        float mn0 = fmaxf(m0, mx0), mn1 = fmaxf(m1, mx1);
        float e0 = __expf(m0 - mn0), e1 = __expf(m1 - mn1);
        m0 = mn0; m1 = mn1;
        float s0 = 0.0f, s1 = 0.0f;
#pragma unroll
        for (int na = 0; na < 8; na++) {
            sc[na][0] = __expf(sc[na][0] - mn0);
            sc[na][1] = __expf(sc[na][1] - mn0);
            sc[na][2] = __expf(sc[na][2] - mn1);
            sc[na][3] = __expf(sc[na][3] - mn1);
            s0 += sc[na][0] + sc[na][1];
            s1 += sc[na][2] + sc[na][3];
        }
        s0 += __shfl_xor_sync(0xffffffffu, s0, 1);
        s0 += __shfl_xor_sync(0xffffffffu, s0, 2);
        s1 += __shfl_xor_sync(0xffffffffu, s1, 1);
        s1 += __shfl_xor_sync(0xffffffffu, s1, 2);
        l0 = l0*e0 + s0;
        l1 = l1*e1 + s1;
#pragma unroll
        for (int na = 0; na < 8; na++) {
            acc_o[na][0] *= e0; acc_o[na][1] *= e0;
            acc_o[na][2] *= e1; acc_o[na][3] *= e1;
        }

#pragma unroll
        for (int kc = 0; kc < 4; kc++) {
            unsigned ph[4], pl[4];
            split2(sc[2*kc][0],   sc[2*kc][1],   ph[0], pl[0]);
            split2(sc[2*kc][2],   sc[2*kc][3],   ph[1], pl[1]);
            split2(sc[2*kc+1][0], sc[2*kc+1][1], ph[2], pl[2]);
            split2(sc[2*kc+1][2], sc[2*kc+1][3], ph[3], pl[3]);
            const unsigned sB = (unsigned)(kc*16*FPAD*2);
            unsigned vbh[4][4], vbl[4][4];
#pragma unroll
            for (int nb = 0; nb < 4; nb++) {
                ldsm4t(vbh[nb], sVh + sB + (unsigned)(nb*32));
                ldsm4t(vbl[nb], sVl + sB + (unsigned)(nb*32));
            }
#pragma unroll
            for (int na = 0; na < 8; na++)
                mma16816(acc_o[na], ph, &vbh[na>>1][(na&1)*2]);
#pragma unroll
            for (int na = 0; na < 8; na++)
                mma16816(acc_o[na], ph, &vbl[na>>1][(na&1)*2]);
#pragma unroll
            for (int na = 0; na < 8; na++)
                mma16816(acc_o[na], pl, &vbh[na>>1][(na&1)*2]);
        }
        __syncthreads();
    }

    const float inv0 = 1.0f / l0, inv1 = 1.0f / l1;
    const size_t row0 = (size_t)(b*SEQ + q0 + r_base);
#pragma unroll
    for (int na = 0; na < 8; na++) {
        const int col = h*64 + na*8 + koff;
        unsigned whb, whh, wlh;
        split3x2(acc_o[na][0]*inv0, acc_o[na][1]*inv0, whb, whh, wlh);
        *(unsigned*)(ohb + row0*DMODEL + col) = whb;
        *(unsigned*)(ohh + row0*DMODEL + col) = whh;
        *(unsigned*)(olh + row0*DMODEL + col) = wlh;
        split3x2(acc_o[na][2]*inv1, acc_o[na][3]*inv1, whb, whh, wlh);
        *(unsigned*)(ohb + (row0+8)*DMODEL + col) = whb;
        *(unsigned*)(ohh + (row0+8)*DMODEL + col) = whh;
        *(unsigned*)(olh + (row0+8)*DMODEL + col) = wlh;
    }
}

// ---------------- positional embedding + 3-form + key-mask bias ----------------
__global__ void posembed_kernel(const float* __restrict__ xin,
                                const int* __restrict__ mask,
                                float* __restrict__ xout,
                                __nv_bfloat16* __restrict__ xhb,
                                __half* __restrict__ xhh,
                                __half* __restrict__ xlh,
                                float* __restrict__ kb)
{
    int b = blockIdx.x;
    int tid = threadIdx.x;                    // 1024 threads
    __shared__ int sc[SEQ];
    int valid = (mask[b*SEQ + tid] != 0) ? 1 : 0;
    kb[b*SEQ + tid] = valid ? 0.0f : -1e30f;
    sc[tid] = valid;
    __syncthreads();
    for (int off = 1; off < SEQ; off <<= 1) {
        int v = (tid >= off) ? sc[tid - off] : 0;
        __syncthreads();
        sc[tid] += v;
        __syncthreads();
    }
    int pos = sc[tid] * valid;
    __syncthreads();
    sc[tid] = pos;
    __syncthreads();

    const float cfreq = -logf(10000.0f) / 255.0f;
    for (int it = 0; it < (SEQ*DMODEL)/SEQ; it++) {
        int idx = it*SEQ + tid;
        int s = idx >> 9;
        int j = idx & 511;
        int p = sc[s];
        size_t g = ((size_t)b*SEQ + s)*DMODEL + j;
        float add = 0.0f;
        if (p > 0) {
            float fr  = expf((float)(j & 255) * cfreq);
            float ang = (float)p * fr;
            add = (j < 256) ? sinf(ang) : cosf(ang);
        }
        float v = xin[g] + add;
        xout[g] = v;
        __nv_bfloat16 h = __float2bfloat16(v);
        float hf = __bfloat162float(h);
        xhb[g] = h;
        xhh[g] = __float2half_rn(hf);
        xlh[g] = __float2half_rn((v - hf)*LOSCALE);
    }
}

// ---------------- out = LN(a + r) * g + b ; warp-per-row, emits 3-form ----------------
__global__ __launch_bounds__(256) void ln_kernel(
    const float* __restrict__ a, const float* __restrict__ r,
    const float* __restrict__ g, const float* __restrict__ be,
    float* __restrict__ out,
    __nv_bfloat16* __restrict__ ohb, __half* __restrict__ ohh, __half* __restrict__ olh)
{
    const int row = blockIdx.x*8 + (threadIdx.x >> 5);
    const int lane = threadIdx.x & 31;
    const size_t base = (size_t)row*DMODEL;
    const float4* a4 = (const float4*)(a + base);
    const float4* r4 = (const float4*)(r + base);

    float4 x[4];
    float s = 0.0f;
#pragma unroll
    for (int k = 0; k < 4; k++) {
        float4 va = a4[lane + k*32];
        float4 vr = r4[lane + k*32];
        x[k] = make_float4(va.x+vr.x, va.y+vr.y, va.z+vr.z, va.w+vr.w);
        s += x[k].x + x[k].y + x[k].z + x[k].w;
    }
#pragma unroll
    for (int o = 16; o; o >>= 1) s += __shfl_xor_sync(0xffffffffu, s, o);
    const float mu = s * (1.0f/512.0f);

    float s2 = 0.0f;
#pragma unroll
    for (int k = 0; k < 4; k++) {
        x[k].x -= mu; x[k].y -= mu; x[k].z -= mu; x[k].w -= mu;
        s2 += x[k].x*x[k].x + x[k].y*x[k].y + x[k].z*x[k].z + x[k].w*x[k].w;
    }
#pragma unroll
    for (int o = 16; o; o >>= 1) s2 += __shfl_xor_sync(0xffffffffu, s2, o);
    const float inv = rsqrtf(s2 * (1.0f/512.0f) + 1e-5f);

    const float4* g4 = (const float4*)g;
    const float4* b4 = (const float4*)be;
    float4* o4 = (float4*)(out + base);
    uint2* ob2 = (uint2*)(ohb + base);
    uint2* oh2 = (uint2*)(ohh + base);
    uint2* ol2 = (uint2*)(olh + base);
#pragma unroll
    for (int k = 0; k < 4; k++) {
        float4 gg = g4[lane + k*32];
        float4 bb = b4[lane + k*32];
        float4 o;
        o.x = x[k].x*inv*gg.x + bb.x;
        o.y = x[k].y*inv*gg.y + bb.y;
        o.z = x[k].z*inv*gg.z + bb.z;
        o.w = x[k].w*inv*gg.w + bb.w;
        o4[lane + k*32] = o;
        unsigned b0, h0, l0, b1, h1, l1;
        split3x2(o.x, o.y, b0, h0, l0);
        split3x2(o.z, o.w, b1, h1, l1);
        ob2[lane + k*32] = make_uint2(b0, b1);
        oh2[lane + k*32] = make_uint2(h0, h1);
        ol2[lane + k*32] = make_uint2(l0, l1);
    }
}

// ---------------- driver ----------------
extern "C" void kernel_launch(void* const* d_in, const int* in_sizes, int n_in,
                              void* d_out, int out_size)
{
    const float* x_in = (const float*)d_in[0];
    const int*   mask = (const int*)d_in[3];
    const float* Wqkv = (const float*)d_in[4];
    const float* Wfc  = (const float*)d_in[5];
    const float* bfc  = (const float*)d_in[6];
    const float* ln1g = (const float*)d_in[7];
    const float* ln1b = (const float*)d_in[8];
    const float* ln2g = (const float*)d_in[9];
    const float* ln2b = (const float*)d_in[10];
    const float* W1   = (const float*)d_in[11];
    const float* b1   = (const float*)d_in[12];
    const float* W2   = (const float*)d_in[13];
    const float* b2   = (const float*)d_in[14];

    float *px, *ptmp, *pkb;
    __nv_bfloat16 *pxhb, *pqh, *pql, *paohb, *pfhb;
    __half *pxhh, *pxlh, *paohh, *paolh, *pfhh, *pflh;
    __nv_bfloat16 *wqhb, *wfhb, *w1hb, *w2hb;
    __half *wqhh, *wqlh, *wfhh, *wflh, *w1hh, *w1lh, *w2hh, *w2lh;
    cudaGetSymbolAddress((void**)&px,    g_x);
    cudaGetSymbolAddress((void**)&pxhb,  g_xhb);
    cudaGetSymbolAddress((void**)&pxhh,  g_xhh);
    cudaGetSymbolAddress((void**)&pxlh,  g_xlh);
    cudaGetSymbolAddress((void**)&pqh,   g_qkvhi);
    cudaGetSymbolAddress((void**)&pql,   g_qkvlo);
    cudaGetSymbolAddress((void**)&pkb,   g_kbias);
    cudaGetSymbolAddress((void**)&paohb, g_aohb);
    cudaGetSymbolAddress((void**)&paohh, g_aohh);
    cudaGetSymbolAddress((void**)&paolh, g_aolh);
    cudaGetSymbolAddress((void**)&ptmp,  g_tmp);
    cudaGetSymbolAddress((void**)&pfhb,  g_fhb);
    cudaGetSymbolAddress((void**)&pfhh,  g_fhh);
    cudaGetSymbolAddress((void**)&pflh,  g_flh);
    cudaGetSymbolAddress((void**)&wqhb,  g_wqhb);
    cudaGetSymbolAddress((void**)&wqhh,  g_wqhh);
    cudaGetSymbolAddress((void**)&wqlh,  g_wqlh);
    cudaGetSymbolAddress((void**)&wfhb,  g_wfhb);
    cudaGetSymbolAddress((void**)&wfhh,  g_wfhh);
    cudaGetSymbolAddress((void**)&wflh,  g_wflh);
    cudaGetSymbolAddress((void**)&w1hb,  g_w1hb);
    cudaGetSymbolAddress((void**)&w1hh,  g_w1hh);
    cudaGetSymbolAddress((void**)&w1lh,  g_w1lh);
    cudaGetSymbolAddress((void**)&w2hb,  g_w2hb);
    cudaGetSymbolAddress((void**)&w2hh,  g_w2hh);
    cudaGetSymbolAddress((void**)&w2lh,  g_w2lh);

    cudaFuncSetAttribute(mma_gemm_kernel<1>, cudaFuncAttributeMaxDynamicSharedMemorySize, GEMM_SMEM);
    cudaFuncSetAttribute(mma_gemm_kernel<2>, cudaFuncAttributeMaxDynamicSharedMemorySize, GEMM_SMEM);
    cudaFuncSetAttribute(mma_gemm_kernel<3>, cudaFuncAttributeMaxDynamicSharedMemorySize, GEMM_SMEM);
    cudaFuncSetAttribute(flash_kernel, cudaFuncAttributeMaxDynamicSharedMemorySize, FLASH_SMEM);

    wprep_all_kernel<<<18432, 256>>>(Wqkv, Wfc, W1, W2,
                                     wqhb, wqhh, wqlh, wfhb, wfhh, wflh,
                                     w1hb, w1hh, w1lh, w2hb, w2hh, w2lh);

    posembed_kernel<<<BATCH, SEQ>>>(x_in, mask, px, pxhb, pxhh, pxlh, pkb);

    for (int l = 0; l < NLAYER; l++) {
        size_t oq = (size_t)l*3*DMODEL*DMODEL;
        size_t of = (size_t)l*DMODEL*DMODEL;
        size_t o1 = (size_t)l*DFF*DMODEL;
        size_t o2 = (size_t)l*DMODEL*DFF;
        // QKV -> bf16 hi/lo pair for flash
        mma_gemm_kernel<3><<<dim3(3*DMODEL/TN, NTOK/TM), 256, GEMM_SMEM>>>(
            pxhb, pxhh, pxlh, wqhb + oq, wqhh + oq, wqlh + oq, nullptr,
            nullptr, pqh, pql, nullptr, nullptr, 3*DMODEL, DMODEL);
        // fused attention -> ao 3-form
        flash_kernel<<<dim3(SEQ/128, BATCH*NHEAD), 256, FLASH_SMEM>>>(
            pqh, pql, pkb, paohb, paohh, paolh);
        // proj + bias -> fp32
        mma_gemm_kernel<1><<<dim3(DMODEL/TN, NTOK/TM), 256, GEMM_SMEM>>>(
            paohb, paohh, paolh, wfhb + of, wfhh + of, wflh + of, bfc + l*DMODEL,
            ptmp, nullptr, nullptr, nullptr, nullptr, DMODEL, DMODEL);
        ln_kernel<<<NTOK/8, 256>>>(ptmp, px, ln1g + l*DMODEL, ln1b + l*DMODEL,
                                   px, pxhb, pxhh, pxlh);
        // FFN up + relu -> 3-form
        mma_gemm_kernel<2><<<dim3(DFF/TN, NTOK/TM), 256, GEMM_SMEM>>>(
            pxhb, pxhh, pxlh, w1hb + o1, w1hh + o1, w1lh + o1, b1 + l*DFF,
            nullptr, pfhb, nullptr, pfhh, pflh, DFF, DMODEL);
        // FFN down + bias -> fp32
        mma_gemm_kernel<1><<<dim3(DMODEL/TN, NTOK/TM), 256, GEMM_SMEM>>>(
            pfhb, pfhh, pflh, w2hb + o2, w2hh + o2, w2lh + o2, b2 + l*DMODEL,
            ptmp, nullptr, nullptr, nullptr, nullptr, DMODEL, DFF);
        ln_kernel<<<NTOK/8, 256>>>(ptmp, px, ln2g + l*DMODEL, ln2b + l*DMODEL,
                                   px, pxhb, pxhh, pxlh);
    }

    cudaMemcpyAsync(d_out, px, (size_t)NTOK*DMODEL*sizeof(float),
                    cudaMemcpyDeviceToDevice);
}

// round 15
// speedup vs baseline: 1.2889x; 1.2889x over previous
#include <cuda_runtime.h>
#include <cuda_bf16.h>
#include <math.h>

#define BATCH  8
#define SEQ    1024
#define DMODEL 512
#define NHEAD  8
#define DHEAD  64
#define NLAYER 6
#define DFF    2048
#define NTOK   (BATCH*SEQ)

// ---- mma.sync GEMM tiling (R12 proven): CTA 128x128, KC=64, ldmatrix ----
#define TM 128
#define TN 128
#define KC 64
#define PADK 72                       // 72 bf16 = 144B row (16B-aligned, conflict-free)
#define MAT_BYTES (128*PADK*2)        // 18432
#define STAGE_BYTES (4*MAT_BYTES)     // 73728
#define GEMM_SMEM (2*STAGE_BYTES)     // 147456

// ---- flash attention tiling ----
#define FPAD 72
#define NTILE 16
#define Q_HI 0
#define Q_LO 9216
#define FSTG(s) (18432 + (s)*18560)
#define KS_HI(s) (FSTG(s))
#define KS_LO(s) (FSTG(s)+4608)
#define VS_HI(s) (FSTG(s)+9216)
#define VS_LO(s) (FSTG(s)+13824)
#define BI_F(s)  (FSTG(s)+18432)
#define FLASH_SMEM (2*(18432 + 2*18560))   // 111104 bytes

// ---------------- scratch (device globals) ----------------
__device__ float g_x     [(size_t)NTOK*DMODEL];
__device__ __nv_bfloat16 g_xhi[(size_t)NTOK*DMODEL];
__device__ __nv_bfloat16 g_xlo[(size_t)NTOK*DMODEL];
__device__ __nv_bfloat16 g_qkvhi[(size_t)NTOK*3*DMODEL];
__device__ __nv_bfloat16 g_qkvlo[(size_t)NTOK*3*DMODEL];
__device__ float g_kbias [(size_t)BATCH*SEQ];
__device__ __nv_bfloat16 g_aohi[(size_t)NTOK*DMODEL];
__device__ __nv_bfloat16 g_aolo[(size_t)NTOK*DMODEL];
__device__ float g_tmp   [(size_t)NTOK*DMODEL];
__device__ __nv_bfloat16 g_fhi[(size_t)NTOK*DFF];
__device__ __nv_bfloat16 g_flo[(size_t)NTOK*DFF];
__device__ __nv_bfloat16 g_wqkvhi[(size_t)NLAYER*3*DMODEL*DMODEL];
__device__ __nv_bfloat16 g_wqkvlo[(size_t)NLAYER*3*DMODEL*DMODEL];
__device__ __nv_bfloat16 g_wfchi [(size_t)NLAYER*DMODEL*DMODEL];
__device__ __nv_bfloat16 g_wfclo [(size_t)NLAYER*DMODEL*DMODEL];
__device__ __nv_bfloat16 g_w1hi  [(size_t)NLAYER*DFF*DMODEL];
__device__ __nv_bfloat16 g_w1lo  [(size_t)NLAYER*DFF*DMODEL];
__device__ __nv_bfloat16 g_w2hi  [(size_t)NLAYER*DMODEL*DFF];
__device__ __nv_bfloat16 g_w2lo  [(size_t)NLAYER*DMODEL*DFF];

// ---------------- helpers ----------------
__device__ __forceinline__ unsigned smem_u32(const void* p){
    unsigned a;
    asm("{ .reg .u64 t; cvta.to.shared.u64 t, %1; cvt.u32.u64 %0, t; }":"=r"(a):"l"(p));
    return a;
}
__device__ __forceinline__ void cp16(unsigned saddr, const void* g){
    asm volatile("cp.async.ca.shared.global [%0], [%1], 16;" :: "r"(saddr), "l"(g));
}
#define CP_COMMIT() asm volatile("cp.async.commit_group;" ::: "memory")
template<int N> __device__ __forceinline__ void cp_wait(){
    asm volatile("cp.async.wait_group %0;" :: "n"(N) : "memory");
}
__device__ __forceinline__ void mma16816(float* d, const unsigned* a, const unsigned* b){
    asm volatile(
        "mma.sync.aligned.m16n8k16.row.col.f32.bf16.bf16.f32 "
        "{%0,%1,%2,%3}, {%4,%5,%6,%7}, {%8,%9}, {%0,%1,%2,%3};"
        : "+f"(d[0]), "+f"(d[1]), "+f"(d[2]), "+f"(d[3])
        : "r"(a[0]), "r"(a[1]), "r"(a[2]), "r"(a[3]), "r"(b[0]), "r"(b[1]));
}
__device__ __forceinline__ void ldsm4(unsigned* r, unsigned saddr){
    asm volatile("ldmatrix.sync.aligned.m8n8.x4.shared.b16 {%0,%1,%2,%3}, [%4];"
        : "=r"(r[0]), "=r"(r[1]), "=r"(r[2]), "=r"(r[3]) : "r"(saddr));
}
__device__ __forceinline__ void ldsm4t(unsigned* r, unsigned saddr){
    asm volatile("ldmatrix.sync.aligned.m8n8.x4.trans.shared.b16 {%0,%1,%2,%3}, [%4];"
        : "=r"(r[0]), "=r"(r[1]), "=r"(r[2]), "=r"(r[3]) : "r"(saddr));
}
__device__ __forceinline__ void split_bf16(float v, __nv_bfloat16& h, __nv_bfloat16& l){
    h = __float2bfloat16(v);
    l = __float2bfloat16(v - __bfloat162float(h));
}
__device__ __forceinline__ void split2(float a, float b, unsigned& hi, unsigned& lo){
    __nv_bfloat16 ha = __float2bfloat16(a), hb = __float2bfloat16(b);
    __nv_bfloat162 hp; hp.x = ha; hp.y = hb;
    __nv_bfloat162 lp;
    lp.x = __float2bfloat16(a - __bfloat162float(ha));
    lp.y = __float2bfloat16(b - __bfloat162float(hb));
    hi = *(unsigned*)&hp; lo = *(unsigned*)&lp;
}

// ---------------- merged weight prep: all 4 tensors in ONE launch ----------------
__global__ __launch_bounds__(256) void wprep_all_kernel(
    const float* __restrict__ Wq, const float* __restrict__ Wf,
    const float* __restrict__ W1, const float* __restrict__ W2,
    __nv_bfloat16* __restrict__ qh, __nv_bfloat16* __restrict__ ql,
    __nv_bfloat16* __restrict__ fh, __nv_bfloat16* __restrict__ fl,
    __nv_bfloat16* __restrict__ w1h, __nv_bfloat16* __restrict__ w1l,
    __nv_bfloat16* __restrict__ w2h, __nv_bfloat16* __restrict__ w2l)
{
    __shared__ float tf[32][33];
    int id = blockIdx.x;
    const float* W; __nv_bfloat16 *Th, *Tl; int K, N;
    if (id < 4608)        { W = Wq; Th = qh;  Tl = ql;  K = 512;  N = 1536; }
    else if (id < 6144)   { id -= 4608;  W = Wf; Th = fh;  Tl = fl;  K = 512;  N = 512; }
    else if (id < 12288)  { id -= 6144;  W = W1; Th = w1h; Tl = w1l; K = 512;  N = 2048; }
    else                  { id -= 12288; W = W2; Th = w2h; Tl = w2l; K = 2048; N = 512; }
    const int tilesN = N >> 5, tilesK = K >> 5;
    const int l = id / (tilesN*tilesK);
    const int rem = id - l*(tilesN*tilesK);
    const int n0 = (rem % tilesN)*32, k0 = (rem / tilesN)*32;
    const int tx = threadIdx.x & 31, ty = threadIdx.x >> 5;
    const float* Wl = W + (size_t)l*K*N;
#pragma unroll
    for (int i = 0; i < 4; i++) {
        int k = k0 + ty*4 + i;
        tf[ty*4+i][tx] = Wl[(size_t)k*N + n0 + tx];
    }
    __syncthreads();
    __nv_bfloat16* Thl = Th + (size_t)l*K*N;
    __nv_bfloat16* Tll = Tl + (size_t)l*K*N;
#pragma unroll
    for (int i = 0; i < 4; i++) {
        int n = n0 + ty*4 + i;
        float v = tf[tx][ty*4+i];
        __nv_bfloat16 h, lo; split_bf16(v, h, lo);
        Thl[(size_t)n*K + k0 + tx] = h;
        Tll[(size_t)n*K + k0 + tx] = lo;
    }
}

// ---------------- mma.sync split-bf16 GEMM (R12 proven + fused residual) ----------------
// EPI: 1 +bias +residual fp32 out; 2 +bias+relu bf16-pair out; 3 bf16-pair out.
template<int EPI>
__global__ __launch_bounds__(256, 1) void mma_gemm_kernel(
    const __nv_bfloat16* __restrict__ Ahi, const __nv_bfloat16* __restrict__ Alo,
    const __nv_bfloat16* __restrict__ Bhi, const __nv_bfloat16* __restrict__ Blo,
    const float* __restrict__ bias,
    const float* __restrict__ resid,
    float* __restrict__ Cf,
    __nv_bfloat16* __restrict__ Chi, __nv_bfloat16* __restrict__ Clo,
    int N, int K)
{
    extern __shared__ char smem[];
    const unsigned sbase = smem_u32(smem);
    const int tid = threadIdx.x;
    const int wid = tid >> 5, lane = tid & 31;
    const int wr = wid & 3;
    const int wc = wid >> 2;
    const int bm = blockIdx.y * TM;
    const int bn = blockIdx.x * TN;

    const int la7  = lane & 7;
    const int la8  = (lane >> 3) & 1;
    const int la16 = lane >> 4;
    const unsigned aoff = (unsigned)((wr*32 + la7 + la8*8)*PADK + la16*8) * 2u;
    const unsigned boff = (unsigned)((wc*64 + la16*8 + la7)*PADK + la8*8) * 2u;

    const int lr = tid >> 3;
    const int lg = tid & 7;

    float acc[2][8][4];
#pragma unroll
    for (int ma = 0; ma < 2; ma++)
#pragma unroll
        for (int na = 0; na < 8; na++)
#pragma unroll
            for (int j = 0; j < 4; j++) acc[ma][na][j] = 0.0f;

    const int NC = K >> 6;

    {
        const unsigned st = sbase;
#pragma unroll
        for (int i = 0; i < 4; i++) {
            int r = lr + i*32;
            unsigned so = (unsigned)(r*144 + lg*16);
            size_t ga = (size_t)(bm + r)*K + lg*8;
            size_t gb = (size_t)(bn + r)*K + lg*8;
            cp16(st + so,                 Ahi + ga);
            cp16(st + MAT_BYTES + so,     Alo + ga);
            cp16(st + 2*MAT_BYTES + so,   Bhi + gb);
            cp16(st + 3*MAT_BYTES + so,   Blo + gb);
        }
        CP_COMMIT();
    }

    for (int c = 0; c < NC; c++) {
        if (c + 1 < NC) {
            const unsigned st = sbase + ((c+1) & 1)*STAGE_BYTES;
            const int k0 = (c+1)*KC;
#pragma unroll
            for (int i = 0; i < 4; i++) {
                int r = lr + i*32;
                unsigned so = (unsigned)(r*144 + lg*16);
                size_t ga = (size_t)(bm + r)*K + k0 + lg*8;
                size_t gb = (size_t)(bn + r)*K + k0 + lg*8;
                cp16(st + so,                 Ahi + ga);
                cp16(st + MAT_BYTES + so,     Alo + ga);
                cp16(st + 2*MAT_BYTES + so,   Bhi + gb);
                cp16(st + 3*MAT_BYTES + so,   Blo + gb);
            }
            CP_COMMIT();
            cp_wait<1>();
        } else {
            cp_wait<0>();
        }
        __syncthreads();

        const unsigned stg = sbase + (c & 1)*STAGE_BYTES;
        const unsigned sAh = stg + aoff;
        const unsigned sAl = stg + MAT_BYTES + aoff;
        const unsigned sBh = stg + 2*MAT_BYTES + boff;
        const unsigned sBl = stg + 3*MAT_BYTES + boff;

#pragma unroll
        for (int ks = 0; ks < 4; ks++) {
            const unsigned kb = (unsigned)(ks*32);
            unsigned ah[2][4], al[2][4];
#pragma unroll
            for (int ma = 0; ma < 2; ma++) {
                ldsm4(ah[ma], sAh + (unsigned)(ma*16*PADK*2) + kb);
                ldsm4(al[ma], sAl + (unsigned)(ma*16*PADK*2) + kb);
            }
            unsigned bh[4][4], bl[4][4];
#pragma unroll
            for (int nb = 0; nb < 4; nb++) {
                ldsm4(bh[nb], sBh + (unsigned)(nb*16*PADK*2) + kb);
                ldsm4(bl[nb], sBl + (unsigned)(nb*16*PADK*2) + kb);
            }
#pragma unroll
            for (int ma = 0; ma < 2; ma++)
#pragma unroll
                for (int na = 0; na < 8; na++)
                    mma16816(acc[ma][na], ah[ma], &bh[na>>1][(na&1)*2]);
#pragma unroll
            for (int ma = 0; ma < 2; ma++)
#pragma unroll
                for (int na = 0; na < 8; na++)
                    mma16816(acc[ma][na], ah[ma], &bl[na>>1][(na&1)*2]);
#pragma unroll
            for (int ma = 0; ma < 2; ma++)
#pragma unroll
                for (int na = 0; na < 8; na++)
                    mma16816(acc[ma][na], al[ma], &bh[na>>1][(na&1)*2]);
        }
        __syncthreads();
    }

    constexpr bool HASBIAS = (EPI == 1 || EPI == 2);
    constexpr bool RESID   = (EPI == 1);
    constexpr bool RELU    = (EPI == 2);
    constexpr bool PAIR    = (EPI == 2 || EPI == 3);
#pragma unroll
    for (int ma = 0; ma < 2; ma++) {
        const int r0 = bm + wr*32 + ma*16 + (lane >> 2);
#pragma unroll
        for (int na = 0; na < 8; na++) {
            const int cc = bn + wc*64 + na*8 + (lane & 3)*2;
            float v0 = acc[ma][na][0], v1 = acc[ma][na][1];
            float v2 = acc[ma][na][2], v3 = acc[ma][na][3];
            if (HASBIAS) {
                float2 bv = *(const float2*)(bias + cc);
                v0 += bv.x; v1 += bv.y; v2 += bv.x; v3 += bv.y;
            }
            if (RESID) {
                float2 rv0 = *(const float2*)(resid + (size_t)r0*N + cc);
                float2 rv1 = *(const float2*)(resid + (size_t)(r0+8)*N + cc);
                v0 += rv0.x; v1 += rv0.y; v2 += rv1.x; v3 += rv1.y;
            }
            if (RELU) {
                v0 = fmaxf(v0, 0.0f); v1 = fmaxf(v1, 0.0f);
                v2 = fmaxf(v2, 0.0f); v3 = fmaxf(v3, 0.0f);
            }
            if (PAIR) {
                unsigned hi, lo;
                split2(v0, v1, hi, lo);
                *(unsigned*)(Chi + (size_t)r0*N + cc) = hi;
                *(unsigned*)(Clo + (size_t)r0*N + cc) = lo;
                split2(v2, v3, hi, lo);
                *(unsigned*)(Chi + (size_t)(r0+8)*N + cc) = hi;
                *(unsigned*)(Clo + (size_t)(r0+8)*N + cc) = lo;
            } else {
                *(float2*)(Cf + (size_t)r0*N + cc)     = make_float2(v0, v1);
                *(float2*)(Cf + (size_t)(r0+8)*N + cc) = make_float2(v2, v3);
            }
        }
    }
}

// ---------------- fused flash attention (R12 proven, unchanged) ----------------
__global__ __launch_bounds__(256, 1) void flash_kernel(
    const __nv_bfloat16* __restrict__ qhi, const __nv_bfloat16* __restrict__ qlo,
    const float* __restrict__ kbias,
    __nv_bfloat16* __restrict__ ohi, __nv_bfloat16* __restrict__ olo)
{
    extern __shared__ char smraw[];
    __nv_bfloat16* sm = (__nv_bfloat16*)smraw;
    const unsigned sb = smem_u32(sm);
    const int tid = threadIdx.x, wid = tid >> 5, lane = tid & 31;
    const int bh = blockIdx.y, b = bh >> 3, h = bh & 7;
    const int q0 = blockIdx.x * 128;
    const int koff = (lane & 3)*2;
    const int r_base = wid*16 + (lane >> 2);

    const int la7  = lane & 7;
    const int la8  = (lane >> 3) & 1;
    const int la16 = lane >> 4;
    const unsigned qoff = (unsigned)((wid*16 + la7 + la8*8)*FPAD + la16*8) * 2u;
    const unsigned kboff = (unsigned)((la16*8 + la7)*FPAD + la8*8) * 2u;
    const unsigned vboff = (unsigned)((la8*8 + la7)*FPAD + la16*8) * 2u;

    auto prefetch_kv = [&](int t, int s){
        const int g = tid & 7;
        const int kt0 = t*64;
#pragma unroll
        for (int i = 0; i < 2; i++) {
            int r = (tid >> 3) + i*32;
            size_t gk = (size_t)(b*SEQ + kt0 + r)*1536 + 512 + h*64 + g*8;
            cp16(sb + 2*(KS_HI(s) + r*FPAD + g*8), qhi + gk);
            cp16(sb + 2*(KS_LO(s) + r*FPAD + g*8), qlo + gk);
            size_t gv = (size_t)(b*SEQ + kt0 + r)*1536 + 1024 + h*64 + g*8;
            cp16(sb + 2*(VS_HI(s) + r*FPAD + g*8), qhi + gv);
            cp16(sb + 2*(VS_LO(s) + r*FPAD + g*8), qlo + gv);
        }
        if (tid >= 240) {
            int j = tid - 240;
            cp16(sb + 2*BI_F(s) + j*16, kbias + b*SEQ + kt0 + j*4);
        }
    };

    {
        const int g = tid & 7;
#pragma unroll
        for (int i = 0; i < 4; i++) {
            int r = (tid >> 3) + i*32;
            size_t gq = (size_t)(b*SEQ + q0 + r)*1536 + h*64 + g*8;
            cp16(sb + 2*(Q_HI + r*FPAD + g*8), qhi + gq);
            cp16(sb + 2*(Q_LO + r*FPAD + g*8), qlo + gq);
        }
        prefetch_kv(0, 0);
        CP_COMMIT();
    }

    float m0 = -1e30f, m1 = -1e30f, l0 = 0.0f, l1 = 0.0f;
    float acc_o[8][4];
#pragma unroll
    for (int na = 0; na < 8; na++)
#pragma unroll
        for (int j = 0; j < 4; j++) acc_o[na][j] = 0.0f;

    for (int t = 0; t < NTILE; t++) {
        if (t + 1 < NTILE) { prefetch_kv(t+1, (t+1)&1); CP_COMMIT(); cp_wait<1>(); }
        else               { cp_wait<0>(); }
        __syncthreads();
        const int s = t & 1;
        const unsigned sQh = sb + 2*Q_HI + qoff;
        const unsigned sQl = sb + 2*Q_LO + qoff;
        const unsigned sKh = sb + 2*KS_HI(s) + kboff;
        const unsigned sKl = sb + 2*KS_LO(s) + kboff;
        const unsigned sVh = sb + 2*VS_HI(s) + vboff;
        const unsigned sVl = sb + 2*VS_LO(s) + vboff;
        const float* bsm = (const float*)(sm + BI_F(s));

        float sc[8][4];
#pragma unroll
        for (int na = 0; na < 8; na++)
#pragma unroll
            for (int j = 0; j < 4; j++) sc[na][j] = 0.0f;

#pragma unroll
        for (int kc = 0; kc < 4; kc++) {
            const unsigned kb = (unsigned)(kc*32);
            unsigned ah[4], al[4];
            ldsm4(ah, sQh + kb);
            ldsm4(al, sQl + kb);
            unsigned kbh[4][4], kbl[4][4];
#pragma unroll
            for (int nb = 0; nb < 4; nb++) {
                ldsm4(kbh[nb], sKh + (unsigned)(nb*16*FPAD*2) + kb);
                ldsm4(kbl[nb], sKl + (unsigned)(nb*16*FPAD*2) + kb);
            }
#pragma unroll
            for (int na = 0; na < 8; na++)
                mma16816(sc[na], ah, &kbh[na>>1][(na&1)*2]);
#pragma unroll
            for (int na = 0; na < 8; na++)
                mma16816(sc[na], ah, &kbl[na>>1][(na&1)*2]);
#pragma unroll
            for (int na = 0; na < 8; na++)
                mma16816(sc[na], al, &kbh[na>>1][(na&1)*2]);
        }

#pragma unroll
        for (int na = 0; na < 8; na++) {
            float b0 = bsm[na*8 + koff], b1 = bsm[na*8 + koff + 1];
            sc[na][0] += b0; sc[na][1] += b1;
            sc[na][2] += b0; sc[na][3] += b1;
        }

        float mx0 = -1e30f, mx1 = -1e30f;
#pragma unroll
        for (int na = 0; na < 8; na++) {
            mx0 = fmaxf(mx0, fmaxf(sc[na][0], sc[na][1]));
            mx1 = fmaxf(mx1, fmaxf(sc[na][2], sc[na][3]));
        }
        mx0 = fmaxf(mx0, __shfl_xor_sync(0xffffffffu, mx0, 1));
        mx0 = fmaxf(mx0, __shfl_xor_sync(0xffffffffu, mx0, 2));
        mx1 = fmaxf(mx1, __shfl_xor_sync(0xffffffffu, mx1, 1));
        mx1 = fmaxf(mx1, __shfl_xor_sync(0xffffffffu, mx1, 2));
        float mn0 = fmaxf(m0, mx0), mn1 = fmaxf(m1, mx1);
        float e0 = __expf(m0 - mn0), e1 = __expf(m1 - mn1);
        m0 = mn0; m1 = mn1;
        float s0 = 0.0f, s1 = 0.0f;
#pragma unroll
        for (int na = 0; na < 8; na++) {
            sc[na][0] = __expf(sc[na][0] - mn0);
            sc[na][1] = __expf(sc[na][1] - mn0);
            sc[na][2] = __expf(sc[na][2] - mn1);
            sc[na][3] = __expf(sc[na][3] - mn1);
            s0 += sc[na][0] + sc[na][1];
            s1 += sc[na][2] + sc[na][3];
        }
        s0 += __shfl_xor_sync(0xffffffffu, s0, 1);
        s0 += __shfl_xor_sync(0xffffffffu, s0, 2);
        s1 += __shfl_xor_sync(0xffffffffu, s1, 1);
        s1 += __shfl_xor_sync(0xffffffffu, s1, 2);
        l0 = l0*e0 + s0;
        l1 = l1*e1 + s1;
#pragma unroll
        for (int na = 0; na < 8; na++) {
            acc_o[na][0] *= e0; acc_o[na][1] *= e0;
            acc_o[na][2] *= e1; acc_o[na][3] *= e1;
        }

#pragma unroll
        for (int kc = 0; kc < 4; kc++) {
            unsigned ph[4], pl[4];
            split2(sc[2*kc][0],   sc[2*kc][1],   ph[0], pl[0]);
            split2(sc[2*kc][2],   sc[2*kc][3],   ph[1], pl[1]);
            split2(sc[2*kc+1][0], sc[2*kc+1][1], ph[2], pl[2]);
            split2(sc[2*kc+1][2], sc[2*kc+1][3], ph[3], pl[3]);
            const unsigned sB = (unsigned)(kc*16*FPAD*2);
            unsigned vbh[4][4], vbl[4][4];
#pragma unroll
            for (int nb = 0; nb < 4; nb++) {
                ldsm4t(vbh[nb], sVh + sB + (unsigned)(nb*32));
                ldsm4t(vbl[nb], sVl + sB + (unsigned)(nb*32));
            }
#pragma unroll
            for (int na = 0; na < 8; na++)
                mma16816(acc_o[na], ph, &vbh[na>>1][(na&1)*2]);
#pragma unroll
            for (int na = 0; na < 8; na++)
                mma16816(acc_o[na], ph, &vbl[na>>1][(na&1)*2]);
#pragma unroll
            for (int na = 0; na < 8; na++)
                mma16816(acc_o[na], pl, &vbh[na>>1][(na&1)*2]);
        }
        __syncthreads();
    }

    const float inv0 = 1.0f / l0, inv1 = 1.0f / l1;
    const size_t row0 = (size_t)(b*SEQ + q0 + r_base);
#pragma unroll
    for (int na = 0; na < 8; na++) {
        const int col = h*64 + na*8 + koff;
        unsigned hi, lo;
        split2(acc_o[na][0]*inv0, acc_o[na][1]*inv0, hi, lo);
        *(unsigned*)(ohi + row0*DMODEL + col) = hi;
        *(unsigned*)(olo + row0*DMODEL + col) = lo;
        split2(acc_o[na][2]*inv1, acc_o[na][3]*inv1, hi, lo);
        *(unsigned*)(ohi + (row0+8)*DMODEL + col) = hi;
        *(unsigned*)(olo + (row0+8)*DMODEL + col) = lo;
    }
}

// ---------------- positional embedding + pair split + key-mask bias ----------------
__global__ void posembed_kernel(const float* __restrict__ xin,
                                const int* __restrict__ mask,
                                float* __restrict__ xout,
                                __nv_bfloat16* __restrict__ xhi,
                                __nv_bfloat16* __restrict__ xlo,
                                float* __restrict__ kb)
{
    int b = blockIdx.x;
    int tid = threadIdx.x;                    // 1024 threads
    __shared__ int sc[SEQ];
    int valid = (mask[b*SEQ + tid] != 0) ? 1 : 0;
    kb[b*SEQ + tid] = valid ? 0.0f : -1e30f;
    sc[tid] = valid;
    __syncthreads();
    for (int off = 1; off < SEQ; off <<= 1) {
        int v = (tid >= off) ? sc[tid - off] : 0;
        __syncthreads();
        sc[tid] += v;
        __syncthreads();
    }
    int pos = sc[tid] * valid;
    __syncthreads();
    sc[tid] = pos;
    __syncthreads();

    const float cfreq = -logf(10000.0f) / 255.0f;
    for (int it = 0; it < (SEQ*DMODEL)/SEQ; it++) {
        int idx = it*SEQ + tid;
        int s = idx >> 9;
        int j = idx & 511;
        int p = sc[s];
        size_t g = ((size_t)b*SEQ + s)*DMODEL + j;
        float add = 0.0f;
        if (p > 0) {
            float fr  = expf((float)(j & 255) * cfreq);
            float ang = (float)p * fr;
            add = (j < 256) ? sinf(ang) : cosf(ang);
        }
        float v = xin[g] + add;
        xout[g] = v;
        __nv_bfloat16 h, l; split_bf16(v, h, l);
        xhi[g] = h; xlo[g] = l;
    }
}

// ---------------- out = LN(a) * g + b ; a already contains the residual sum ----------------
__global__ __launch_bounds__(256) void ln_kernel(
    const float* __restrict__ a,
    const float* __restrict__ g, const float* __restrict__ be,
    float* __restrict__ out,
    __nv_bfloat16* __restrict__ ohi, __nv_bfloat16* __restrict__ olo)
{
    const int row = blockIdx.x*8 + (threadIdx.x >> 5);
    const int lane = threadIdx.x & 31;
    const size_t base = (size_t)row*DMODEL;
    const float4* a4 = (const float4*)(a + base);

    float4 x[4];
    float s = 0.0f;
#pragma unroll
    for (int k = 0; k < 4; k++) {
        x[k] = a4[lane + k*32];
        s += x[k].x + x[k].y + x[k].z + x[k].w;
    }
#pragma unroll
    for (int o = 16; o; o >>= 1) s += __shfl_xor_sync(0xffffffffu, s, o);
    const float mu = s * (1.0f/512.0f);

    float s2 = 0.0f;
#pragma unroll
    for (int k = 0; k < 4; k++) {
        x[k].x -= mu; x[k].y -= mu; x[k].z -= mu; x[k].w -= mu;
        s2 += x[k].x*x[k].x + x[k].y*x[k].y + x[k].z*x[k].z + x[k].w*x[k].w;
    }
#pragma unroll
    for (int o = 16; o; o >>= 1) s2 += __shfl_xor_sync(0xffffffffu, s2, o);
    const float inv = rsqrtf(s2 * (1.0f/512.0f) + 1e-5f);

    const float4* g4 = (const float4*)g;
    const float4* b4 = (const float4*)be;
    float4* o4 = (float4*)(out + base);
    uint2* oh2 = (uint2*)(ohi + base);
    uint2* ol2 = (uint2*)(olo + base);
#pragma unroll
    for (int k = 0; k < 4; k++) {
        float4 gg = g4[lane + k*32];
        float4 bb = b4[lane + k*32];
        float4 o;
        o.x = x[k].x*inv*gg.x + bb.x;
        o.y = x[k].y*inv*gg.y + bb.y;
        o.z = x[k].z*inv*gg.z + bb.z;
        o.w = x[k].w*inv*gg.w + bb.w;
        o4[lane + k*32] = o;
        unsigned h0, l0, h1, l1;
        split2(o.x, o.y, h0, l0);
        split2(o.z, o.w, h1, l1);
        oh2[lane + k*32] = make_uint2(h0, h1);
        ol2[lane + k*32] = make_uint2(l0, l1);
    }
}

// ---------------- driver ----------------
extern "C" void kernel_launch(void* const* d_in, const int* in_sizes, int n_in,
                              void* d_out, int out_size)
{
    const float* x_in = (const float*)d_in[0];
    const int*   mask = (const int*)d_in[3];
    const float* Wqkv = (const float*)d_in[4];
    const float* Wfc  = (const float*)d_in[5];
    const float* bfc  = (const float*)d_in[6];
    const float* ln1g = (const float*)d_in[7];
    const float* ln1b = (const float*)d_in[8];
    const float* ln2g = (const float*)d_in[9];
    const float* ln2b = (const float*)d_in[10];
    const float* W1   = (const float*)d_in[11];
    const float* b1   = (const float*)d_in[12];
    const float* W2   = (const float*)d_in[13];
    const float* b2   = (const float*)d_in[14];

    float *px, *ptmp, *pkb;
    __nv_bfloat16 *pxhi, *pxlo, *pqh, *pql, *paohi, *paolo, *pfhi, *pflo;
    __nv_bfloat16 *wqh, *wql, *wfh, *wfl, *w1h, *w1l, *w2h, *w2l;
    cudaGetSymbolAddress((void**)&px,    g_x);
    cudaGetSymbolAddress((void**)&pxhi,  g_xhi);
    cudaGetSymbolAddress((void**)&pxlo,  g_xlo);
    cudaGetSymbolAddress((void**)&pqh,   g_qkvhi);
    cudaGetSymbolAddress((void**)&pql,   g_qkvlo);
    cudaGetSymbolAddress((void**)&pkb,   g_kbias);
    cudaGetSymbolAddress((void**)&paohi, g_aohi);
    cudaGetSymbolAddress((void**)&paolo, g_aolo);
    cudaGetSymbolAddress((void**)&ptmp,  g_tmp);
    cudaGetSymbolAddress((void**)&pfhi,  g_fhi);
    cudaGetSymbolAddress((void**)&pflo,  g_flo);
    cudaGetSymbolAddress((void**)&wqh,   g_wqkvhi);
    cudaGetSymbolAddress((void**)&wql,   g_wqkvlo);
    cudaGetSymbolAddress((void**)&wfh,   g_wfchi);
    cudaGetSymbolAddress((void**)&wfl,   g_wfclo);
    cudaGetSymbolAddress((void**)&w1h,   g_w1hi);
    cudaGetSymbolAddress((void**)&w1l,   g_w1lo);
    cudaGetSymbolAddress((void**)&w2h,   g_w2hi);
    cudaGetSymbolAddress((void**)&w2l,   g_w2lo);

    cudaFuncSetAttribute(mma_gemm_kernel<1>, cudaFuncAttributeMaxDynamicSharedMemorySize, GEMM_SMEM);
    cudaFuncSetAttribute(mma_gemm_kernel<2>, cudaFuncAttributeMaxDynamicSharedMemorySize, GEMM_SMEM);
    cudaFuncSetAttribute(mma_gemm_kernel<3>, cudaFuncAttributeMaxDynamicSharedMemorySize, GEMM_SMEM);
    cudaFuncSetAttribute(flash_kernel, cudaFuncAttributeMaxDynamicSharedMemorySize, FLASH_SMEM);

    wprep_all_kernel<<<18432, 256>>>(Wqkv, Wfc, W1, W2,
                                     wqh, wql, wfh, wfl, w1h, w1l, w2h, w2l);

    posembed_kernel<<<BATCH, SEQ>>>(x_in, mask, px, pxhi, pxlo, pkb);

    for (int l = 0; l < NLAYER; l++) {
        size_t oq = (size_t)l*3*DMODEL*DMODEL;
        size_t of = (size_t)l*DMODEL*DMODEL;
        size_t o1 = (size_t)l*DFF*DMODEL;
        size_t o2 = (size_t)l*DMODEL*DFF;
        // QKV -> bf16 hi/lo pair
        mma_gemm_kernel<3><<<dim3(3*DMODEL/TN, NTOK/TM), 256, GEMM_SMEM>>>(
            pxhi, pxlo, wqh + oq, wql + oq, nullptr, nullptr,
            nullptr, pqh, pql, 3*DMODEL, DMODEL);
        // fused attention
        flash_kernel<<<dim3(SEQ/128, BATCH*NHEAD), 256, FLASH_SMEM>>>(
            pqh, pql, pkb, paohi, paolo);
        // proj + bias + residual(px) -> fp32 sum
        mma_gemm_kernel<1><<<dim3(DMODEL/TN, NTOK/TM), 256, GEMM_SMEM>>>(
            paohi, paolo, wfh + of, wfl + of, bfc + l*DMODEL, px,
            ptmp, nullptr, nullptr, DMODEL, DMODEL);
        ln_kernel<<<NTOK/8, 256>>>(ptmp, ln1g + l*DMODEL, ln1b + l*DMODEL,
                                   px, pxhi, pxlo);
        // FFN up + relu -> bf16 pair
        mma_gemm_kernel<2><<<dim3(DFF/TN, NTOK/TM), 256, GEMM_SMEM>>>(
            pxhi, pxlo, w1h + o1, w1l + o1, b1 + l*DFF, nullptr,
            nullptr, pfhi, pflo, DFF, DMODEL);
        // FFN down + bias + residual(px) -> fp32 sum
        mma_gemm_kernel<1><<<dim3(DMODEL/TN, NTOK/TM), 256, GEMM_SMEM>>>(
            pfhi, pflo, w2h + o2, w2l + o2, b2 + l*DMODEL, px,
            ptmp, nullptr, nullptr, DMODEL, DFF);
        // last LN writes straight into d_out (no trailing memcpy)
        float* lnout = (l == NLAYER-1) ? (float*)d_out : px;
        ln_kernel<<<NTOK/8, 256>>>(ptmp, ln2g + l*DMODEL, ln2b + l*DMODEL,
                                   lnout, pxhi, pxlo);
    }
}

// round 17
// speedup vs baseline: 1.3125x; 1.0183x over previous
#include <cuda_runtime.h>
#include <cuda_bf16.h>
#include <math.h>

#define BATCH  8
#define SEQ    1024
#define DMODEL 512
#define NHEAD  8
#define DHEAD  64
#define NLAYER 6
#define DFF    2048
#define NTOK   (BATCH*SEQ)

// ---- mma.sync GEMM tiling (R12 proven): CTA 128x128, KC=64, ldmatrix ----
#define TM 128
#define TN 128
#define KC 64
#define PADK 72
#define MAT_BYTES (128*PADK*2)        // 18432
#define STAGE_BYTES (4*MAT_BYTES)     // 73728
#define GEMM_SMEM (2*STAGE_BYTES)     // 147456

// ---- flash attention tiling: Q-tile 64 rows, 4 warps, 2 CTAs/SM ----
#define FPAD 72
#define NTILE 16
#define Q_HI 0
#define Q_LO 4608
#define FSTG(s) (9216 + (s)*18560)
#define KS_HI(s) (FSTG(s))
#define KS_LO(s) (FSTG(s)+4608)
#define VS_HI(s) (FSTG(s)+9216)
#define VS_LO(s) (FSTG(s)+13824)
#define BI_F(s)  (FSTG(s)+18432)
#define FLASH_SMEM (2*(9216 + 2*18560))   // 92672 bytes; x2 CTAs fits 228KB

// ---------------- scratch (device globals) ----------------
__device__ __nv_bfloat16 g_xhi[(size_t)NTOK*DMODEL];
__device__ __nv_bfloat16 g_xlo[(size_t)NTOK*DMODEL];
__device__ __nv_bfloat16 g_qkvhi[(size_t)NTOK*3*DMODEL];
__device__ __nv_bfloat16 g_qkvlo[(size_t)NTOK*3*DMODEL];
__device__ float g_kbias [(size_t)BATCH*SEQ];
__device__ __nv_bfloat16 g_aohi[(size_t)NTOK*DMODEL];
__device__ __nv_bfloat16 g_aolo[(size_t)NTOK*DMODEL];
__device__ float g_tmp   [(size_t)NTOK*DMODEL];
__device__ __nv_bfloat16 g_fhi[(size_t)NTOK*DFF];
__device__ __nv_bfloat16 g_flo[(size_t)NTOK*DFF];
__device__ __nv_bfloat16 g_wqkvhi[(size_t)NLAYER*3*DMODEL*DMODEL];
__device__ __nv_bfloat16 g_wqkvlo[(size_t)NLAYER*3*DMODEL*DMODEL];
__device__ __nv_bfloat16 g_wfchi [(size_t)NLAYER*DMODEL*DMODEL];
__device__ __nv_bfloat16 g_wfclo [(size_t)NLAYER*DMODEL*DMODEL];
__device__ __nv_bfloat16 g_w1hi  [(size_t)NLAYER*DFF*DMODEL];
__device__ __nv_bfloat16 g_w1lo  [(size_t)NLAYER*DFF*DMODEL];
__device__ __nv_bfloat16 g_w2hi  [(size_t)NLAYER*DMODEL*DFF];
__device__ __nv_bfloat16 g_w2lo  [(size_t)NLAYER*DMODEL*DFF];

// ---------------- helpers ----------------
__device__ __forceinline__ unsigned smem_u32(const void* p){
    unsigned a;
    asm("{ .reg .u64 t; cvta.to.shared.u64 t, %1; cvt.u32.u64 %0, t; }":"=r"(a):"l"(p));
    return a;
}
__device__ __forceinline__ void cp16(unsigned saddr, const void* g){
    asm volatile("cp.async.ca.shared.global [%0], [%1], 16;" :: "r"(saddr), "l"(g));
}
#define CP_COMMIT() asm volatile("cp.async.commit_group;" ::: "memory")
template<int N> __device__ __forceinline__ void cp_wait(){
    asm volatile("cp.async.wait_group %0;" :: "n"(N) : "memory");
}
__device__ __forceinline__ void mma16816(float* d, const unsigned* a, const unsigned* b){
    asm volatile(
        "mma.sync.aligned.m16n8k16.row.col.f32.bf16.bf16.f32 "
        "{%0,%1,%2,%3}, {%4,%5,%6,%7}, {%8,%9}, {%0,%1,%2,%3};"
        : "+f"(d[0]), "+f"(d[1]), "+f"(d[2]), "+f"(d[3])
        : "r"(a[0]), "r"(a[1]), "r"(a[2]), "r"(a[3]), "r"(b[0]), "r"(b[1]));
}
__device__ __forceinline__ void ldsm4(unsigned* r, unsigned saddr){
    asm volatile("ldmatrix.sync.aligned.m8n8.x4.shared.b16 {%0,%1,%2,%3}, [%4];"
        : "=r"(r[0]), "=r"(r[1]), "=r"(r[2]), "=r"(r[3]) : "r"(saddr));
}
__device__ __forceinline__ void ldsm4t(unsigned* r, unsigned saddr){
    asm volatile("ldmatrix.sync.aligned.m8n8.x4.trans.shared.b16 {%0,%1,%2,%3}, [%4];"
        : "=r"(r[0]), "=r"(r[1]), "=r"(r[2]), "=r"(r[3]) : "r"(saddr));
}
__device__ __forceinline__ void split_bf16(float v, __nv_bfloat16& h, __nv_bfloat16& l){
    h = __float2bfloat16(v);
    l = __float2bfloat16(v - __bfloat162float(h));
}
__device__ __forceinline__ void split2(float a, float b, unsigned& hi, unsigned& lo){
    __nv_bfloat16 ha = __float2bfloat16(a), hb = __float2bfloat16(b);
    __nv_bfloat162 hp; hp.x = ha; hp.y = hb;
    __nv_bfloat162 lp;
    lp.x = __float2bfloat16(a - __bfloat162float(ha));
    lp.y = __float2bfloat16(b - __bfloat162float(hb));
    hi = *(unsigned*)&hp; lo = *(unsigned*)&lp;
}

// ---------------- merged weight prep ----------------
__global__ __launch_bounds__(256) void wprep_all_kernel(
    const float* __restrict__ Wq, const float* __restrict__ Wf,
    const float* __restrict__ W1, const float* __restrict__ W2,
    __nv_bfloat16* __restrict__ qh, __nv_bfloat16* __restrict__ ql,
    __nv_bfloat16* __restrict__ fh, __nv_bfloat16* __restrict__ fl,
    __nv_bfloat16* __restrict__ w1h, __nv_bfloat16* __restrict__ w1l,
    __nv_bfloat16* __restrict__ w2h, __nv_bfloat16* __restrict__ w2l)
{
    __shared__ float tf[32][33];
    int id = blockIdx.x;
    const float* W; __nv_bfloat16 *Th, *Tl; int K, N;
    if (id < 4608)        { W = Wq; Th = qh;  Tl = ql;  K = 512;  N = 1536; }
    else if (id < 6144)   { id -= 4608;  W = Wf; Th = fh;  Tl = fl;  K = 512;  N = 512; }
    else if (id < 12288)  { id -= 6144;  W = W1; Th = w1h; Tl = w1l; K = 512;  N = 2048; }
    else                  { id -= 12288; W = W2; Th = w2h; Tl = w2l; K = 2048; N = 512; }
    const int tilesN = N >> 5, tilesK = K >> 5;
    const int l = id / (tilesN*tilesK);
    const int rem = id - l*(tilesN*tilesK);
    const int n0 = (rem % tilesN)*32, k0 = (rem / tilesN)*32;
    const int tx = threadIdx.x & 31, ty = threadIdx.x >> 5;
    const float* Wl = W + (size_t)l*K*N;
#pragma unroll
    for (int i = 0; i < 4; i++) {
        int k = k0 + ty*4 + i;
        tf[ty*4+i][tx] = Wl[(size_t)k*N + n0 + tx];
    }
    __syncthreads();
    __nv_bfloat16* Thl = Th + (size_t)l*K*N;
    __nv_bfloat16* Tll = Tl + (size_t)l*K*N;
#pragma unroll
    for (int i = 0; i < 4; i++) {
        int n = n0 + ty*4 + i;
        float v = tf[tx][ty*4+i];
        __nv_bfloat16 h, lo; split_bf16(v, h, lo);
        Thl[(size_t)n*K + k0 + tx] = h;
        Tll[(size_t)n*K + k0 + tx] = lo;
    }
}

// ---------------- mma.sync split-bf16 GEMM ----------------
// EPI: 1 +bias +residual(bf16 hi/lo recon) fp32 out; 2 +bias+relu pair out; 3 pair out.
template<int EPI>
__global__ __launch_bounds__(256, 1) void mma_gemm_kernel(
    const __nv_bfloat16* __restrict__ Ahi, const __nv_bfloat16* __restrict__ Alo,
    const __nv_bfloat16* __restrict__ Bhi, const __nv_bfloat16* __restrict__ Blo,
    const float* __restrict__ bias,
    const __nv_bfloat16* __restrict__ reshi, const __nv_bfloat16* __restrict__ reslo,
    float* __restrict__ Cf,
    __nv_bfloat16* __restrict__ Chi, __nv_bfloat16* __restrict__ Clo,
    int N, int K)
{
    extern __shared__ char smem[];
    const unsigned sbase = smem_u32(smem);
    const int tid = threadIdx.x;
    const int wid = tid >> 5, lane = tid & 31;
    const int wr = wid & 3;
    const int wc = wid >> 2;
    const int bm = blockIdx.y * TM;
    const int bn = blockIdx.x * TN;

    const int la7  = lane & 7;
    const int la8  = (lane >> 3) & 1;
    const int la16 = lane >> 4;
    const unsigned aoff = (unsigned)((wr*32 + la7 + la8*8)*PADK + la16*8) * 2u;
    const unsigned boff = (unsigned)((wc*64 + la16*8 + la7)*PADK + la8*8) * 2u;

    const int lr = tid >> 3;
    const int lg = tid & 7;

    float acc[2][8][4];
#pragma unroll
    for (int ma = 0; ma < 2; ma++)
#pragma unroll
        for (int na = 0; na < 8; na++)
#pragma unroll
            for (int j = 0; j < 4; j++) acc[ma][na][j] = 0.0f;

    const int NC = K >> 6;

    {
        const unsigned st = sbase;
#pragma unroll
        for (int i = 0; i < 4; i++) {
            int r = lr + i*32;
            unsigned so = (unsigned)(r*144 + lg*16);
            size_t ga = (size_t)(bm + r)*K + lg*8;
            size_t gb = (size_t)(bn + r)*K + lg*8;
            cp16(st + so,                 Ahi + ga);
            cp16(st + MAT_BYTES + so,     Alo + ga);
            cp16(st + 2*MAT_BYTES + so,   Bhi + gb);
            cp16(st + 3*MAT_BYTES + so,   Blo + gb);
        }
        CP_COMMIT();
    }

    for (int c = 0; c < NC; c++) {
        if (c + 1 < NC) {
            const unsigned st = sbase + ((c+1) & 1)*STAGE_BYTES;
            const int k0 = (c+1)*KC;
#pragma unroll
            for (int i = 0; i < 4; i++) {
                int r = lr + i*32;
                unsigned so = (unsigned)(r*144 + lg*16);
                size_t ga = (size_t)(bm + r)*K + k0 + lg*8;
                size_t gb = (size_t)(bn + r)*K + k0 + lg*8;
                cp16(st + so,                 Ahi + ga);
                cp16(st + MAT_BYTES + so,     Alo + ga);
                cp16(st + 2*MAT_BYTES + so,   Bhi + gb);
                cp16(st + 3*MAT_BYTES + so,   Blo + gb);
            }
            CP_COMMIT();
            cp_wait<1>();
        } else {
            cp_wait<0>();
        }
        __syncthreads();

        const unsigned stg = sbase + (c & 1)*STAGE_BYTES;
        const unsigned sAh = stg + aoff;
        const unsigned sAl = stg + MAT_BYTES + aoff;
        const unsigned sBh = stg + 2*MAT_BYTES + boff;
        const unsigned sBl = stg + 3*MAT_BYTES + boff;

#pragma unroll
        for (int ks = 0; ks < 4; ks++) {
            const unsigned kb = (unsigned)(ks*32);
            unsigned ah[2][4], al[2][4];
#pragma unroll
            for (int ma = 0; ma < 2; ma++) {
                ldsm4(ah[ma], sAh + (unsigned)(ma*16*PADK*2) + kb);
                ldsm4(al[ma], sAl + (unsigned)(ma*16*PADK*2) + kb);
            }
            unsigned bh[4][4], bl[4][4];
#pragma unroll
            for (int nb = 0; nb < 4; nb++) {
                ldsm4(bh[nb], sBh + (unsigned)(nb*16*PADK*2) + kb);
                ldsm4(bl[nb], sBl + (unsigned)(nb*16*PADK*2) + kb);
            }
#pragma unroll
            for (int ma = 0; ma < 2; ma++)
#pragma unroll
                for (int na = 0; na < 8; na++)
                    mma16816(acc[ma][na], ah[ma], &bh[na>>1][(na&1)*2]);
#pragma unroll
            for (int ma = 0; ma < 2; ma++)
#pragma unroll
                for (int na = 0; na < 8; na++)
                    mma16816(acc[ma][na], ah[ma], &bl[na>>1][(na&1)*2]);
#pragma unroll
            for (int ma = 0; ma < 2; ma++)
#pragma unroll
                for (int na = 0; na < 8; na++)
                    mma16816(acc[ma][na], al[ma], &bh[na>>1][(na&1)*2]);
        }
        __syncthreads();
    }

    constexpr bool HASBIAS = (EPI == 1 || EPI == 2);
    constexpr bool RESID   = (EPI == 1);
    constexpr bool RELU    = (EPI == 2);
    constexpr bool PAIR    = (EPI == 2 || EPI == 3);
#pragma unroll
    for (int ma = 0; ma < 2; ma++) {
        const int r0 = bm + wr*32 + ma*16 + (lane >> 2);
#pragma unroll
        for (int na = 0; na < 8; na++) {
            const int cc = bn + wc*64 + na*8 + (lane & 3)*2;
            float v0 = acc[ma][na][0], v1 = acc[ma][na][1];
            float v2 = acc[ma][na][2], v3 = acc[ma][na][3];
            if (HASBIAS) {
                float2 bv = *(const float2*)(bias + cc);
                v0 += bv.x; v1 += bv.y; v2 += bv.x; v3 += bv.y;
            }
            if (RESID) {
                __nv_bfloat162 rh0 = *(const __nv_bfloat162*)(reshi + (size_t)r0*N + cc);
                __nv_bfloat162 rl0 = *(const __nv_bfloat162*)(reslo + (size_t)r0*N + cc);
                __nv_bfloat162 rh1 = *(const __nv_bfloat162*)(reshi + (size_t)(r0+8)*N + cc);
                __nv_bfloat162 rl1 = *(const __nv_bfloat162*)(reslo + (size_t)(r0+8)*N + cc);
                v0 += __bfloat162float(rh0.x) + __bfloat162float(rl0.x);
                v1 += __bfloat162float(rh0.y) + __bfloat162float(rl0.y);
                v2 += __bfloat162float(rh1.x) + __bfloat162float(rl1.x);
                v3 += __bfloat162float(rh1.y) + __bfloat162float(rl1.y);
            }
            if (RELU) {
                v0 = fmaxf(v0, 0.0f); v1 = fmaxf(v1, 0.0f);
                v2 = fmaxf(v2, 0.0f); v3 = fmaxf(v3, 0.0f);
            }
            if (PAIR) {
                unsigned hi, lo;
                split2(v0, v1, hi, lo);
                *(unsigned*)(Chi + (size_t)r0*N + cc) = hi;
                *(unsigned*)(Clo + (size_t)r0*N + cc) = lo;
                split2(v2, v3, hi, lo);
                *(unsigned*)(Chi + (size_t)(r0+8)*N + cc) = hi;
                *(unsigned*)(Clo + (size_t)(r0+8)*N + cc) = lo;
            } else {
                *(float2*)(Cf + (size_t)r0*N + cc)     = make_float2(v0, v1);
                *(float2*)(Cf + (size_t)(r0+8)*N + cc) = make_float2(v2, v3);
            }
        }
    }
}

// ---------------- fused flash attention: 64-row Q tiles, 4 warps, 2 CTAs/SM ----------------
__global__ __launch_bounds__(128, 2) void flash_kernel(
    const __nv_bfloat16* __restrict__ qhi, const __nv_bfloat16* __restrict__ qlo,
    const float* __restrict__ kbias,
    __nv_bfloat16* __restrict__ ohi, __nv_bfloat16* __restrict__ olo)
{
    extern __shared__ char smraw[];
    __nv_bfloat16* sm = (__nv_bfloat16*)smraw;
    const unsigned sb = smem_u32(sm);
    const int tid = threadIdx.x, wid = tid >> 5, lane = tid & 31;
    const int bh = blockIdx.y, b = bh >> 3, h = bh & 7;
    const int q0 = blockIdx.x * 64;
    const int koff = (lane & 3)*2;
    const int r_base = wid*16 + (lane >> 2);

    const int la7  = lane & 7;
    const int la8  = (lane >> 3) & 1;
    const int la16 = lane >> 4;
    const unsigned qoff = (unsigned)((wid*16 + la7 + la8*8)*FPAD + la16*8) * 2u;
    const unsigned kboff = (unsigned)((la16*8 + la7)*FPAD + la8*8) * 2u;
    const unsigned vboff = (unsigned)((la8*8 + la7)*FPAD + la16*8) * 2u;

    auto prefetch_kv = [&](int t, int s){
        const int g = tid & 7;
        const int kt0 = t*64;
#pragma unroll
        for (int i = 0; i < 4; i++) {
            int r = (tid >> 3) + i*16;
            size_t gk = (size_t)(b*SEQ + kt0 + r)*1536 + 512 + h*64 + g*8;
            cp16(sb + 2*(KS_HI(s) + r*FPAD + g*8), qhi + gk);
            cp16(sb + 2*(KS_LO(s) + r*FPAD + g*8), qlo + gk);
            size_t gv = (size_t)(b*SEQ + kt0 + r)*1536 + 1024 + h*64 + g*8;
            cp16(sb + 2*(VS_HI(s) + r*FPAD + g*8), qhi + gv);
            cp16(sb + 2*(VS_LO(s) + r*FPAD + g*8), qlo + gv);
        }
        if (tid >= 112) {
            int j = tid - 112;
            cp16(sb + 2*BI_F(s) + j*16, kbias + b*SEQ + kt0 + j*4);
        }
    };

    {
        const int g = tid & 7;
#pragma unroll
        for (int i = 0; i < 4; i++) {
            int r = (tid >> 3) + i*16;
            size_t gq = (size_t)(b*SEQ + q0 + r)*1536 + h*64 + g*8;
            cp16(sb + 2*(Q_HI + r*FPAD + g*8), qhi + gq);
            cp16(sb + 2*(Q_LO + r*FPAD + g*8), qlo + gq);
        }
        prefetch_kv(0, 0);
        CP_COMMIT();
    }

    float m0 = -1e30f, m1 = -1e30f, l0 = 0.0f, l1 = 0.0f;
    float acc_o[8][4];
#pragma unroll
    for (int na = 0; na < 8; na++)
#pragma unroll
        for (int j = 0; j < 4; j++) acc_o[na][j] = 0.0f;

    for (int t = 0; t < NTILE; t++) {
        if (t + 1 < NTILE) { prefetch_kv(t+1, (t+1)&1); CP_COMMIT(); cp_wait<1>(); }
        else               { cp_wait<0>(); }
        __syncthreads();
        const int s = t & 1;
        const unsigned sQh = sb + 2*Q_HI + qoff;
        const unsigned sQl = sb + 2*Q_LO + qoff;
        const unsigned sKh = sb + 2*KS_HI(s) + kboff;
        const unsigned sKl = sb + 2*KS_LO(s) + kboff;
        const unsigned sVh = sb + 2*VS_HI(s) + vboff;
        const unsigned sVl = sb + 2*VS_LO(s) + vboff;
        const float* bsm = (const float*)(sm + BI_F(s));

        float sc[8][4];
#pragma unroll
        for (int na = 0; na < 8; na++)
#pragma unroll
            for (int j = 0; j < 4; j++) sc[na][j] = 0.0f;

#pragma unroll
        for (int kc = 0; kc < 4; kc++) {
            const unsigned kb = (unsigned)(kc*32);
            unsigned ah[4], al[4];
            ldsm4(ah, sQh + kb);
            ldsm4(al, sQl + kb);
            unsigned kbh[4][4], kbl[4][4];
#pragma unroll
            for (int nb = 0; nb < 4; nb++) {
                ldsm4(kbh[nb], sKh + (unsigned)(nb*16*FPAD*2) + kb);
                ldsm4(kbl[nb], sKl + (unsigned)(nb*16*FPAD*2) + kb);
            }
#pragma unroll
            for (int na = 0; na < 8; na++)
                mma16816(sc[na], ah, &kbh[na>>1][(na&1)*2]);
#pragma unroll
            for (int na = 0; na < 8; na++)
                mma16816(sc[na], ah, &kbl[na>>1][(na&1)*2]);
#pragma unroll
            for (int na = 0; na < 8; na++)
                mma16816(sc[na], al, &kbh[na>>1][(na&1)*2]);
        }

#pragma unroll
        for (int na = 0; na < 8; na++) {
            float b0 = bsm[na*8 + koff], b1 = bsm[na*8 + koff + 1];
            sc[na][0] += b0; sc[na][1] += b1;
            sc[na][2] += b0; sc[na][3] += b1;
        }

        float mx0 = -1e30f, mx1 = -1e30f;
#pragma unroll
        for (int na = 0; na < 8; na++) {
            mx0 = fmaxf(mx0, fmaxf(sc[na][0], sc[na][1]));
            mx1 = fmaxf(mx1, fmaxf(sc[na][2], sc[na][3]));
        }
        mx0 = fmaxf(mx0, __shfl_xor_sync(0xffffffffu, mx0, 1));
        mx0 = fmaxf(mx0, __shfl_xor_sync(0xffffffffu, mx0, 2));
        mx1 = fmaxf(mx1, __shfl_xor_sync(0xffffffffu, mx1, 1));
        mx1 = fmaxf(mx1, __shfl_xor_sync(0xffffffffu, mx1, 2));
        float mn0 = fmaxf(m0, mx0), mn1 = fmaxf(m1, mx1);
        float e0 = __expf(m0 - mn0), e1 = __expf(m1 - mn1);
        m0 = mn0; m1 = mn1;
        float s0 = 0.0f, s1 = 0.0f;
#pragma unroll
        for (int na = 0; na < 8; na++) {
            sc[na][0] = __expf(sc[na][0] - mn0);
            sc[na][1] = __expf(sc[na][1] - mn0);
            sc[na][2] = __expf(sc[na][2] - mn1);
            sc[na][3] = __expf(sc[na][3] - mn1);
            s0 += sc[na][0] + sc[na][1];
            s1 += sc[na][2] + sc[na][3];
        }
        s0 += __shfl_xor_sync(0xffffffffu, s0, 1);
        s0 += __shfl_xor_sync(0xffffffffu, s0, 2);
        s1 += __shfl_xor_sync(0xffffffffu, s1, 1);
        s1 += __shfl_xor_sync(0xffffffffu, s1, 2);
        l0 = l0*e0 + s0;
        l1 = l1*e1 + s1;
#pragma unroll
        for (int na = 0; na < 8; na++) {
            acc_o[na][0] *= e0; acc_o[na][1] *= e0;
            acc_o[na][2] *= e1; acc_o[na][3] *= e1;
        }

#pragma unroll
        for (int kc = 0; kc < 4; kc++) {
            unsigned ph[4], pl[4];
            split2(sc[2*kc][0],   sc[2*kc][1],   ph[0], pl[0]);
            split2(sc[2*kc][2],   sc[2*kc][3],   ph[1], pl[1]);
            split2(sc[2*kc+1][0], sc[2*kc+1][1], ph[2], pl[2]);
            split2(sc[2*kc+1][2], sc[2*kc+1][3], ph[3], pl[3]);
            const unsigned sB = (unsigned)(kc*16*FPAD*2);
            unsigned vbh[4][4], vbl[4][4];
#pragma unroll
            for (int nb = 0; nb < 4; nb++) {
                ldsm4t(vbh[nb], sVh + sB + (unsigned)(nb*32));
                ldsm4t(vbl[nb], sVl + sB + (unsigned)(nb*32));
            }
#pragma unroll
            for (int na = 0; na < 8; na++)
                mma16816(acc_o[na], ph, &vbh[na>>1][(na&1)*2]);
#pragma unroll
            for (int na = 0; na < 8; na++)
                mma16816(acc_o[na], ph, &vbl[na>>1][(na&1)*2]);
#pragma unroll
            for (int na = 0; na < 8; na++)
                mma16816(acc_o[na], pl, &vbh[na>>1][(na&1)*2]);
        }
        __syncthreads();
    }

    const float inv0 = 1.0f / l0, inv1 = 1.0f / l1;
    const size_t row0 = (size_t)(b*SEQ + q0 + r_base);
#pragma unroll
    for (int na = 0; na < 8; na++) {
        const int col = h*64 + na*8 + koff;
        unsigned hi, lo;
        split2(acc_o[na][0]*inv0, acc_o[na][1]*inv0, hi, lo);
        *(unsigned*)(ohi + row0*DMODEL + col) = hi;
        *(unsigned*)(olo + row0*DMODEL + col) = lo;
        split2(acc_o[na][2]*inv1, acc_o[na][3]*inv1, hi, lo);
        *(unsigned*)(ohi + (row0+8)*DMODEL + col) = hi;
        *(unsigned*)(olo + (row0+8)*DMODEL + col) = lo;
    }
}

// ---------------- positional embedding -> bf16 pair + key-mask bias ----------------
__global__ void posembed_kernel(const float* __restrict__ xin,
                                const int* __restrict__ mask,
                                __nv_bfloat16* __restrict__ xhi,
                                __nv_bfloat16* __restrict__ xlo,
                                float* __restrict__ kb)
{
    int b = blockIdx.x;
    int tid = threadIdx.x;                    // 1024 threads
    __shared__ int sc[SEQ];
    int valid = (mask[b*SEQ + tid] != 0) ? 1 : 0;
    kb[b*SEQ + tid] = valid ? 0.0f : -1e30f;
    sc[tid] = valid;
    __syncthreads();
    for (int off = 1; off < SEQ; off <<= 1) {
        int v = (tid >= off) ? sc[tid - off] : 0;
        __syncthreads();
        sc[tid] += v;
        __syncthreads();
    }
    int pos = sc[tid] * valid;
    __syncthreads();
    sc[tid] = pos;
    __syncthreads();

    const float cfreq = -logf(10000.0f) / 255.0f;
    for (int it = 0; it < (SEQ*DMODEL)/SEQ; it++) {
        int idx = it*SEQ + tid;
        int s = idx >> 9;
        int j = idx & 511;
        int p = sc[s];
        size_t g = ((size_t)b*SEQ + s)*DMODEL + j;
        float add = 0.0f;
        if (p > 0) {
            float fr  = expf((float)(j & 255) * cfreq);
            float ang = (float)p * fr;
            add = (j < 256) ? sinf(ang) : cosf(ang);
        }
        float v = xin[g] + add;
        __nv_bfloat16 h, l; split_bf16(v, h, l);
        xhi[g] = h; xlo[g] = l;
    }
}

// ---------------- LN(a)*g+b -> bf16 pair (+ optional fp32 out for final layer) ----------------
__global__ __launch_bounds__(256) void ln_kernel(
    const float* __restrict__ a,
    const float* __restrict__ g, const float* __restrict__ be,
    float* __restrict__ out,
    __nv_bfloat16* __restrict__ ohi, __nv_bfloat16* __restrict__ olo)
{
    const int row = blockIdx.x*8 + (threadIdx.x >> 5);
    const int lane = threadIdx.x & 31;
    const size_t base = (size_t)row*DMODEL;
    const float4* a4 = (const float4*)(a + base);

    float4 x[4];
    float s = 0.0f;
#pragma unroll
    for (int k = 0; k < 4; k++) {
        x[k] = a4[lane + k*32];
        s += x[k].x + x[k].y + x[k].z + x[k].w;
    }
#pragma unroll
    for (int o = 16; o; o >>= 1) s += __shfl_xor_sync(0xffffffffu, s, o);
    const float mu = s * (1.0f/512.0f);

    float s2 = 0.0f;
#pragma unroll
    for (int k = 0; k < 4; k++) {
        x[k].x -= mu; x[k].y -= mu; x[k].z -= mu; x[k].w -= mu;
        s2 += x[k].x*x[k].x + x[k].y*x[k].y + x[k].z*x[k].z + x[k].w*x[k].w;
    }
#pragma unroll
    for (int o = 16; o; o >>= 1) s2 += __shfl_xor_sync(0xffffffffu, s2, o);
    const float inv = rsqrtf(s2 * (1.0f/512.0f) + 1e-5f);

    const float4* g4 = (const float4*)g;
    const float4* b4 = (const float4*)be;
    uint2* oh2 = (uint2*)(ohi + base);
    uint2* ol2 = (uint2*)(olo + base);
#pragma unroll
    for (int k = 0; k < 4; k++) {
        float4 gg = g4[lane + k*32];
        float4 bb = b4[lane + k*32];
        float4 o;
        o.x = x[k].x*inv*gg.x + bb.x;
        o.y = x[k].y*inv*gg.y + bb.y;
        o.z = x[k].z*inv*gg.z + bb.z;
        o.w = x[k].w*inv*gg.w + bb.w;
        if (out) ((float4*)(out + base))[lane + k*32] = o;
        unsigned h0, l0, h1, l1;
        split2(o.x, o.y, h0, l0);
        split2(o.z, o.w, h1, l1);
        oh2[lane + k*32] = make_uint2(h0, h1);
        ol2[lane + k*32] = make_uint2(l0, l1);
    }
}

// ---------------- driver ----------------
extern "C" void kernel_launch(void* const* d_in, const int* in_sizes, int n_in,
                              void* d_out, int out_size)
{
    const float* x_in = (const float*)d_in[0];
    const int*   mask = (const int*)d_in[3];
    const float* Wqkv = (const float*)d_in[4];
    const float* Wfc  = (const float*)d_in[5];
    const float* bfc  = (const float*)d_in[6];
    const float* ln1g = (const float*)d_in[7];
    const float* ln1b = (const float*)d_in[8];
    const float* ln2g = (const float*)d_in[9];
    const float* ln2b = (const float*)d_in[10];
    const float* W1   = (const float*)d_in[11];
    const float* b1   = (const float*)d_in[12];
    const float* W2   = (const float*)d_in[13];
    const float* b2   = (const float*)d_in[14];

    float *ptmp, *pkb;
    __nv_bfloat16 *pxhi, *pxlo, *pqh, *pql, *paohi, *paolo, *pfhi, *pflo;
    __nv_bfloat16 *wqh, *wql, *wfh, *wfl, *w1h, *w1l, *w2h, *w2l;
    cudaGetSymbolAddress((void**)&pxhi,  g_xhi);
    cudaGetSymbolAddress((void**)&pxlo,  g_xlo);
    cudaGetSymbolAddress((void**)&pqh,   g_qkvhi);
    cudaGetSymbolAddress((void**)&pql,   g_qkvlo);
    cudaGetSymbolAddress((void**)&pkb,   g_kbias);
    cudaGetSymbolAddress((void**)&paohi, g_aohi);
    cudaGetSymbolAddress((void**)&paolo, g_aolo);
    cudaGetSymbolAddress((void**)&ptmp,  g_tmp);
    cudaGetSymbolAddress((void**)&pfhi,  g_fhi);
    cudaGetSymbolAddress((void**)&pflo,  g_flo);
    cudaGetSymbolAddress((void**)&wqh,   g_wqkvhi);
    cudaGetSymbolAddress((void**)&wql,   g_wqkvlo);
    cudaGetSymbolAddress((void**)&wfh,   g_wfchi);
    cudaGetSymbolAddress((void**)&wfl,   g_wfclo);
    cudaGetSymbolAddress((void**)&w1h,   g_w1hi);
    cudaGetSymbolAddress((void**)&w1l,   g_w1lo);
    cudaGetSymbolAddress((void**)&w2h,   g_w2hi);
    cudaGetSymbolAddress((void**)&w2l,   g_w2lo);

    cudaFuncSetAttribute(mma_gemm_kernel<1>, cudaFuncAttributeMaxDynamicSharedMemorySize, GEMM_SMEM);
    cudaFuncSetAttribute(mma_gemm_kernel<2>, cudaFuncAttributeMaxDynamicSharedMemorySize, GEMM_SMEM);
    cudaFuncSetAttribute(mma_gemm_kernel<3>, cudaFuncAttributeMaxDynamicSharedMemorySize, GEMM_SMEM);
    cudaFuncSetAttribute(flash_kernel, cudaFuncAttributeMaxDynamicSharedMemorySize, FLASH_SMEM);

    wprep_all_kernel<<<18432, 256>>>(Wqkv, Wfc, W1, W2,
                                     wqh, wql, wfh, wfl, w1h, w1l, w2h, w2l);

    posembed_kernel<<<BATCH, SEQ>>>(x_in, mask, pxhi, pxlo, pkb);

    for (int l = 0; l < NLAYER; l++) {
        size_t oq = (size_t)l*3*DMODEL*DMODEL;
        size_t of = (size_t)l*DMODEL*DMODEL;
        size_t o1 = (size_t)l*DFF*DMODEL;
        size_t o2 = (size_t)l*DMODEL*DFF;
        // QKV -> bf16 hi/lo pair
        mma_gemm_kernel<3><<<dim3(3*DMODEL/TN, NTOK/TM), 256, GEMM_SMEM>>>(
            pxhi, pxlo, wqh + oq, wql + oq, nullptr, nullptr, nullptr,
            nullptr, pqh, pql, 3*DMODEL, DMODEL);
        // fused attention (64-row Q tiles, 2 CTAs/SM)
        flash_kernel<<<dim3(SEQ/64, BATCH*NHEAD), 128, FLASH_SMEM>>>(
            pqh, pql, pkb, paohi, paolo);
        // proj + bias + residual(x via hi/lo recon) -> fp32 sum
        mma_gemm_kernel<1><<<dim3(DMODEL/TN, NTOK/TM), 256, GEMM_SMEM>>>(
            paohi, paolo, wfh + of, wfl + of, bfc + l*DMODEL, pxhi, pxlo,
            ptmp, nullptr, nullptr, DMODEL, DMODEL);
        ln_kernel<<<NTOK/8, 256>>>(ptmp, ln1g + l*DMODEL, ln1b + l*DMODEL,
                                   nullptr, pxhi, pxlo);
        // FFN up + relu -> bf16 pair
        mma_gemm_kernel<2><<<dim3(DFF/TN, NTOK/TM), 256, GEMM_SMEM>>>(
            pxhi, pxlo, w1h + o1, w1l + o1, b1 + l*DFF, nullptr, nullptr,
            nullptr, pfhi, pflo, DFF, DMODEL);
        // FFN down + bias + residual(x via hi/lo recon) -> fp32 sum
        mma_gemm_kernel<1><<<dim3(DMODEL/TN, NTOK/TM), 256, GEMM_SMEM>>>(
            pfhi, pflo, w2h + o2, w2l + o2, b2 + l*DMODEL, pxhi, pxlo,
            ptmp, nullptr, nullptr, DMODEL, DFF);
        // final-layer LN writes fp32 straight to d_out
        float* lnout = (l == NLAYER-1) ? (float*)d_out : nullptr;
        ln_kernel<<<NTOK/8, 256>>>(ptmp, ln2g + l*DMODEL, ln2b + l*DMODEL,
                                   lnout, pxhi, pxlo);
    }
}